// round 1
// baseline (speedup 1.0000x reference)
#include <cuda_runtime.h>
#include <math.h>

#define H      1024
#define INNER  2048
#define NST    16
#define CONVK  4
#define DTR    64
#define BATCH  2
#define SEQ    1024
#define TOK    (BATCH*SEQ)   // 2048

// ---------------- scratch (device globals; no allocation allowed) ----------
__device__ float g_normed[TOK * H];          //  8 MB
__device__ float g_xz[TOK * 2 * INNER];      // 32 MB
__device__ float g_xa[TOK * INNER];          // 16 MB
__device__ float g_bc[TOK * 2 * NST];        // 256 KB
__device__ float g_dtr[TOK * DTR];           // 512 KB
__device__ float g_dt[TOK * INNER];          // 16 MB
__device__ float g_dtmean[TOK];
__device__ float g_gated[TOK * INNER];       // 16 MB

// ---------------- LayerNorm ------------------------------------------------
__global__ void layernorm_k(const float* __restrict__ x,
                            const float* __restrict__ w,
                            const float* __restrict__ b,
                            float* __restrict__ out) {
    int row = blockIdx.x;
    const float* xr = x + row * H;
    float s = 0.f, s2 = 0.f;
    for (int i = threadIdx.x; i < H; i += 256) {
        float v = xr[i];
        s += v; s2 += v * v;
    }
    #pragma unroll
    for (int o = 16; o > 0; o >>= 1) {
        s  += __shfl_down_sync(0xffffffffu, s,  o);
        s2 += __shfl_down_sync(0xffffffffu, s2, o);
    }
    __shared__ float rs[8], rs2[8], stat[2];
    int wid = threadIdx.x >> 5, lid = threadIdx.x & 31;
    if (lid == 0) { rs[wid] = s; rs2[wid] = s2; }
    __syncthreads();
    if (threadIdx.x == 0) {
        float a = 0.f, c = 0.f;
        #pragma unroll
        for (int i = 0; i < 8; i++) { a += rs[i]; c += rs2[i]; }
        float mu = a / (float)H;
        stat[0] = mu;
        stat[1] = rsqrtf(c / (float)H - mu * mu + 1e-5f);
    }
    __syncthreads();
    float mu = stat[0], rstd = stat[1];
    for (int i = threadIdx.x; i < H; i += 256)
        out[row * H + i] = (xr[i] - mu) * rstd * w[i] + b[i];
}

// ---------------- fp32 tiled GEMM: C[M,N] = A[M,K]*B[K,N] + bias[N] --------
// BM=BN=128, BK=8, 256 threads, 8x8 per thread. M,N mult of 128, K mult of 8.
__global__ void gemm_k(const float* __restrict__ A,
                       const float* __restrict__ B,
                       const float* __restrict__ bias,
                       float* __restrict__ C,
                       int M, int N, int K) {
    __shared__ float As[8][128];
    __shared__ float Bs[8][128];
    int tid = threadIdx.x;
    int tx = tid & 15;        // 0..15
    int ty = tid >> 4;        // 0..15
    int m0 = blockIdx.y * 128;
    int n0 = blockIdx.x * 128;

    float acc[8][8];
    #pragma unroll
    for (int i = 0; i < 8; i++)
        #pragma unroll
        for (int j = 0; j < 8; j++) acc[i][j] = 0.f;

    int ar = tid >> 1;            // 0..127
    int ac = (tid & 1) * 4;       // 0 or 4
    int br = tid >> 5;            // 0..7
    int bcn = (tid & 31) * 4;     // 0..124

    const float* Ap = A + (size_t)(m0 + ar) * K + ac;
    const float* Bp = B + (size_t)br * N + n0 + bcn;

    for (int k0 = 0; k0 < K; k0 += 8) {
        float4 av = *(const float4*)Ap; Ap += 8;
        float4 bv = *(const float4*)Bp; Bp += (size_t)8 * N;
        As[ac + 0][ar] = av.x;
        As[ac + 1][ar] = av.y;
        As[ac + 2][ar] = av.z;
        As[ac + 3][ar] = av.w;
        *(float4*)&Bs[br][bcn] = bv;
        __syncthreads();
        #pragma unroll
        for (int k = 0; k < 8; k++) {
            float4 a0 = *(const float4*)&As[k][ty * 8];
            float4 a1 = *(const float4*)&As[k][ty * 8 + 4];
            float4 b0 = *(const float4*)&Bs[k][tx * 8];
            float4 b1 = *(const float4*)&Bs[k][tx * 8 + 4];
            float avv[8] = {a0.x, a0.y, a0.z, a0.w, a1.x, a1.y, a1.z, a1.w};
            float bvv[8] = {b0.x, b0.y, b0.z, b0.w, b1.x, b1.y, b1.z, b1.w};
            #pragma unroll
            for (int i = 0; i < 8; i++)
                #pragma unroll
                for (int j = 0; j < 8; j++)
                    acc[i][j] = fmaf(avv[i], bvv[j], acc[i][j]);
        }
        __syncthreads();
    }

    #pragma unroll
    for (int i = 0; i < 8; i++) {
        int row = m0 + ty * 8 + i;
        #pragma unroll
        for (int j = 0; j < 8; j++) {
            int col = n0 + tx * 8 + j;
            C[(size_t)row * N + col] = acc[i][j] + bias[col];
        }
    }
}

// ---------------- causal conv (4-tap, depthwise) + SiLU --------------------
__global__ void conv_silu_k(const float* __restrict__ xz,
                            const float* __restrict__ cw,
                            const float* __restrict__ cb,
                            float* __restrict__ xa) {
    int idx = blockIdx.x * 256 + threadIdx.x;       // over TOK*INNER
    int d = idx & (INNER - 1);
    int tg = idx >> 11;                             // token 0..2047
    int b = tg >> 10;
    int t = tg & (SEQ - 1);
    float4 w4 = *(const float4*)(cw + d * 4);
    float wv[4] = {w4.x, w4.y, w4.z, w4.w};
    float acc = cb[d];
    #pragma unroll
    for (int k = 0; k < 4; k++) {
        int tt = t - 3 + k;
        if (tt >= 0)
            acc = fmaf(xz[((size_t)(b * SEQ + tt)) * (2 * INNER) + d], wv[k], acc);
    }
    float s = acc / (1.f + __expf(-acc));
    xa[idx] = s;
}

// ---------------- small projections: out[t,j]=sum_k A[t,k]*W[k,j]+bias[j] --
template <int NO>
__global__ void rowdot_k(const float* __restrict__ A,
                         const float* __restrict__ W,
                         const float* __restrict__ bias,
                         float* __restrict__ out, int K) {
    const int TPB = 256 / NO;                    // tokens per block
    int token = blockIdx.x * TPB + threadIdx.x / NO;
    int j = threadIdx.x % NO;
    const float* a = A + (size_t)token * K;
    float a0 = 0.f, a1 = 0.f, a2 = 0.f, a3 = 0.f;
    #pragma unroll 4
    for (int k = 0; k < K; k += 4) {
        float4 av = *(const float4*)(a + k);
        a0 = fmaf(av.x, W[(size_t)(k + 0) * NO + j], a0);
        a1 = fmaf(av.y, W[(size_t)(k + 1) * NO + j], a1);
        a2 = fmaf(av.z, W[(size_t)(k + 2) * NO + j], a2);
        a3 = fmaf(av.w, W[(size_t)(k + 3) * NO + j], a3);
    }
    out[(size_t)token * NO + j] = a0 + a1 + a2 + a3 + bias[j];
}

// ---------------- softplus + clip (in place) + per-token mean --------------
__global__ void softplus_mean_k(float* __restrict__ dt,
                                float* __restrict__ dtmean) {
    int t = blockIdx.x;
    float s = 0.f;
    for (int i = threadIdx.x; i < INNER; i += 256) {
        float v = dt[(size_t)t * INNER + i];
        float sp = (v > 20.f) ? v : log1pf(__expf(v));
        sp = fminf(fmaxf(sp, 0.001f), 0.1f);
        dt[(size_t)t * INNER + i] = sp;
        s += sp;
    }
    #pragma unroll
    for (int o = 16; o > 0; o >>= 1)
        s += __shfl_down_sync(0xffffffffu, s, o);
    __shared__ float rs[8];
    int wid = threadIdx.x >> 5, lid = threadIdx.x & 31;
    if (lid == 0) rs[wid] = s;
    __syncthreads();
    if (threadIdx.x == 0) {
        float a = 0.f;
        #pragma unroll
        for (int i = 0; i < 8; i++) a += rs[i];
        dtmean[t] = a / (float)INNER;
    }
}

// ---------------- selective scan + gating -----------------------------------
// grid (INNER/64, BATCH), block 64. Thread owns (b,d), 16 states in registers.
__global__ void scan_k(const float* __restrict__ dt,
                       const float* __restrict__ xa,
                       const float* __restrict__ dtmean,
                       const float* __restrict__ bc,
                       const float* __restrict__ xz,
                       float* __restrict__ gated) {
    int b = blockIdx.y;
    int d = blockIdx.x * 64 + threadIdx.x;
    __shared__ float sBC[64 * 32];
    __shared__ float sDM[64];

    float h[16];
    #pragma unroll
    for (int n = 0; n < 16; n++) h[n] = 0.f;

    int base = b * SEQ;
    for (int tc = 0; tc < SEQ; tc += 64) {
        __syncthreads();
        for (int i = threadIdx.x; i < 64 * 32; i += 64)
            sBC[i] = bc[(size_t)(base + tc) * 32 + i];
        sDM[threadIdx.x] = dtmean[base + tc + threadIdx.x];
        __syncthreads();

        #pragma unroll 4
        for (int tt = 0; tt < 64; tt++) {
            int t = base + tc + tt;
            float dtv = dt[(size_t)t * INNER + d];
            float xav = xa[(size_t)t * INNER + d];
            float zv  = xz[(size_t)t * (2 * INNER) + INNER + d];

            float e1 = __expf(-dtv);
            float e2 = e1 * e1, e4 = e2 * e2, e8 = e4 * e4;
            float e3 = e2 * e1, e5 = e4 * e1, e6 = e4 * e2, e7 = e4 * e3;
            float ab[16] = {e1, e2, e3, e4, e5, e6, e7, e8,
                            e8 * e1, e8 * e2, e8 * e3, e8 * e4,
                            e8 * e5, e8 * e6, e8 * e7, e8 * e8};

            float bxv = sDM[tt] * xav;
            const float* Bm = &sBC[tt * 32];
            const float* Cm = Bm + 16;

            float y0 = 0.f, y1 = 0.f, y2 = 0.f, y3 = 0.f;
            #pragma unroll
            for (int n = 0; n < 16; n += 4) {
                h[n + 0] = fmaf(ab[n + 0], h[n + 0], bxv * Bm[n + 0]);
                h[n + 1] = fmaf(ab[n + 1], h[n + 1], bxv * Bm[n + 1]);
                h[n + 2] = fmaf(ab[n + 2], h[n + 2], bxv * Bm[n + 2]);
                h[n + 3] = fmaf(ab[n + 3], h[n + 3], bxv * Bm[n + 3]);
                y0 = fmaf(h[n + 0], Cm[n + 0], y0);
                y1 = fmaf(h[n + 1], Cm[n + 1], y1);
                y2 = fmaf(h[n + 2], Cm[n + 2], y2);
                y3 = fmaf(h[n + 3], Cm[n + 3], y3);
            }
            float y = (y0 + y1) + (y2 + y3);
            float sz = zv / (1.f + __expf(-zv));
            gated[(size_t)t * INNER + d] = y * sz;
        }
    }
}

// ---------------- launch -----------------------------------------------------
extern "C" void kernel_launch(void* const* d_in, const int* in_sizes, int n_in,
                              void* d_out, int out_size) {
    const float* x      = (const float*)d_in[0];
    const float* norm_w = (const float*)d_in[1];
    const float* norm_b = (const float*)d_in[2];
    const float* in_w   = (const float*)d_in[3];
    const float* in_b   = (const float*)d_in[4];
    const float* conv_w = (const float*)d_in[5];
    const float* conv_b = (const float*)d_in[6];
    const float* bc_w   = (const float*)d_in[7];
    const float* bc_b   = (const float*)d_in[8];
    const float* dtr_w  = (const float*)d_in[9];
    const float* dtr_b  = (const float*)d_in[10];
    const float* dt_w   = (const float*)d_in[11];
    const float* dt_b   = (const float*)d_in[12];
    const float* out_w  = (const float*)d_in[13];
    const float* out_b  = (const float*)d_in[14];
    float* out = (float*)d_out;

    float *normed, *xz, *xa, *bcv, *dtrv, *dtv, *dtmean, *gated;
    cudaGetSymbolAddress((void**)&normed, g_normed);
    cudaGetSymbolAddress((void**)&xz,     g_xz);
    cudaGetSymbolAddress((void**)&xa,     g_xa);
    cudaGetSymbolAddress((void**)&bcv,    g_bc);
    cudaGetSymbolAddress((void**)&dtrv,   g_dtr);
    cudaGetSymbolAddress((void**)&dtv,    g_dt);
    cudaGetSymbolAddress((void**)&dtmean, g_dtmean);
    cudaGetSymbolAddress((void**)&gated,  g_gated);

    // 1. LayerNorm
    layernorm_k<<<TOK, 256>>>(x, norm_w, norm_b, normed);
    // 2. in-proj GEMM: (2048,1024) @ (1024,4096)
    gemm_k<<<dim3(4096 / 128, TOK / 128), 256>>>(normed, in_w, in_b, xz,
                                                 TOK, 2 * INNER, H);
    // 3. conv + SiLU
    conv_silu_k<<<(TOK * INNER) / 256, 256>>>(xz, conv_w, conv_b, xa);
    // 4. B/C projection: (2048,2048) @ (2048,32)
    rowdot_k<32><<<TOK / 8, 256>>>(xa, bc_w, bc_b, bcv, INNER);
    // 5. dt rank projection: (2048,2048) @ (2048,64)
    rowdot_k<64><<<TOK / 4, 256>>>(xa, dtr_w, dtr_b, dtrv, INNER);
    // 6. dt expansion GEMM: (2048,64) @ (64,2048)
    gemm_k<<<dim3(INNER / 128, TOK / 128), 256>>>(dtrv, dt_w, dt_b, dtv,
                                                  TOK, INNER, DTR);
    // 7. softplus + clip + per-token mean
    softplus_mean_k<<<TOK, 256>>>(dtv, dtmean);
    // 8. selective scan + gating
    scan_k<<<dim3(INNER / 64, BATCH), 64>>>(dtv, xa, dtmean, bcv, xz, gated);
    // 9. out-proj GEMM: (2048,2048) @ (2048,1024)
    gemm_k<<<dim3(H / 128, TOK / 128), 256>>>(gated, out_w, out_b, out,
                                              TOK, H, INNER);
}

// round 3
// speedup vs baseline: 1.5589x; 1.5589x over previous
#include <cuda_runtime.h>
#include <cuda_bf16.h>
#include <cstdint>
#include <math.h>

#define H      1024
#define INNER  2048
#define NST    16
#define DTR    64
#define BATCH  2
#define SEQ    1024
#define TOK    (BATCH*SEQ)   // 2048

// ======================= PTX helpers (plain sm_103 legal) ====================
__device__ __forceinline__ uint32_t smem_u32(const void* p) {
    uint32_t a;
    asm("{ .reg .u64 t; cvta.to.shared.u64 t, %1; cvt.u32.u64 %0, t; }"
        : "=r"(a) : "l"(p));
    return a;
}
__device__ __forceinline__ void cp16(uint32_t saddr, const void* g) {
    asm volatile("cp.async.cg.shared.global [%0], [%1], 16;"
                 :: "r"(saddr), "l"(g) : "memory");
}
#define CP_COMMIT() asm volatile("cp.async.commit_group;" ::: "memory")
#define CP_WAIT0()  asm volatile("cp.async.wait_group 0;" ::: "memory")

__device__ __forceinline__ void ldsm_x4(uint32_t* r, uint32_t addr) {
    asm volatile("ldmatrix.sync.aligned.m8n8.x4.shared.b16 {%0,%1,%2,%3}, [%4];"
                 : "=r"(r[0]), "=r"(r[1]), "=r"(r[2]), "=r"(r[3]) : "r"(addr));
}
__device__ __forceinline__ void mma_bf16(float* c, const uint32_t* a, const uint32_t* b) {
    asm volatile("mma.sync.aligned.m16n8k16.row.col.f32.bf16.bf16.f32 "
                 "{%0,%1,%2,%3}, {%4,%5,%6,%7}, {%8,%9}, {%0,%1,%2,%3};"
                 : "+f"(c[0]), "+f"(c[1]), "+f"(c[2]), "+f"(c[3])
                 : "r"(a[0]), "r"(a[1]), "r"(a[2]), "r"(a[3]),
                   "r"(b[0]), "r"(b[1]));
}
__device__ __forceinline__ void split_bf16(float v, __nv_bfloat16& h, __nv_bfloat16& l) {
    h = __float2bfloat16(v);
    l = __float2bfloat16(v - __bfloat162float(h));
}

// ======================= scratch buffers ====================================
__device__ __align__(16) __nv_bfloat16 gA_in [TOK * 3 * H];
__device__ __align__(16) __nv_bfloat16 gB_in [2 * INNER * 3 * H];
__device__ __align__(16) float         g_xz  [TOK * 2 * INNER];
__device__ __align__(16) float         g_xa  [TOK * INNER];
__device__ __align__(16) __nv_bfloat16 gA_xa [TOK * 3 * INNER];
__device__ __align__(16) __nv_bfloat16 gB_bc [128 * 3 * INNER];
__device__ __align__(16) float         g_bcdtr[TOK * 96];
__device__                float        g_bias96[96];
__device__ __align__(16) __nv_bfloat16 gA_dtr[TOK * 3 * DTR];
__device__ __align__(16) __nv_bfloat16 gB_dt [INNER * 3 * DTR];
__device__ __align__(16) float         g_dt  [TOK * INNER];
__device__                float        g_dtmean[TOK];
__device__ __align__(16) __nv_bfloat16 gA_out[TOK * 3 * INNER];
__device__ __align__(16) __nv_bfloat16 gB_out[H * 3 * INNER];

// ======================= warp-MMA bf16x3 GEMM ================================
// C[M,N] = A'[M,K']*B'[N,K']^T + bias.  BM=BN=128, BK=64, 256 threads.
#define BM   128
#define BN   128
#define BKE  64
#define LDSTR 72                       // padded smem row stride in bf16
#define BUFE ((BM + BN) * LDSTR)       // elements per buffer

__global__ void __launch_bounds__(256)
gemm3_k(const __nv_bfloat16* __restrict__ A, const __nv_bfloat16* __restrict__ B,
        const float* __restrict__ bias, float* __restrict__ C,
        int K, int ldc, int nvalid) {
    extern __shared__ __align__(16) __nv_bfloat16 sm[];
    const uint32_t smb = smem_u32(sm);

    const int tid = threadIdx.x;
    const int lane = tid & 31, wid = tid >> 5;
    const int m0 = blockIdx.y * BM, n0 = blockIdx.x * BN;
    const int wm = (wid & 3) * 32;       // warp row offset in tile
    const int wn = (wid >> 2) * 64;      // warp col offset in tile

    float acc[2][8][4];
    #pragma unroll
    for (int i = 0; i < 2; i++)
        #pragma unroll
        for (int j = 0; j < 8; j++)
            #pragma unroll
            for (int k = 0; k < 4; k++) acc[i][j][k] = 0.f;

    const int nc = K >> 6;

    // gmem->smem loader: 4 chunks of 16B for A, 4 for B per thread
    auto load_tile = [&](int buf, int kc) {
        const __nv_bfloat16* Ag = A + (size_t)m0 * K + kc * BKE;
        const __nv_bfloat16* Bg = B + (size_t)n0 * K + kc * BKE;
        uint32_t sa = smb + buf * BUFE * 2;
        uint32_t sbb = sa + BM * LDSTR * 2;
        #pragma unroll
        for (int i = 0; i < 4; i++) {
            int ci = tid + i * 256;
            int row = ci >> 3, c8 = ci & 7;
            uint32_t so = (uint32_t)(row * LDSTR + c8 * 8) * 2;
            cp16(sa + so,  Ag + (size_t)row * K + c8 * 8);
            cp16(sbb + so, Bg + (size_t)row * K + c8 * 8);
        }
    };

    load_tile(0, 0);
    CP_COMMIT();

    for (int c = 0; c < nc; c++) {
        CP_WAIT0();
        __syncthreads();
        if (c + 1 < nc) { load_tile((c + 1) & 1, c + 1); CP_COMMIT(); }

        const int buf = c & 1;
        const uint32_t a_base = smb + buf * BUFE * 2;
        const uint32_t b_base = a_base + BM * LDSTR * 2;

        #pragma unroll
        for (int kk = 0; kk < 4; kk++) {
            uint32_t afr[2][4];
            #pragma unroll
            for (int mt = 0; mt < 2; mt++) {
                int row = wm + mt * 16 + (lane & 15);
                int col = kk * 16 + (lane >> 4) * 8;
                ldsm_x4(afr[mt], a_base + (uint32_t)(row * LDSTR + col) * 2);
            }
            uint32_t bfr[8][2];
            #pragma unroll
            for (int p = 0; p < 4; p++) {
                int g = lane >> 3, idx = lane & 7;
                int row = wn + p * 16 + idx + (g >> 1) * 8;
                int col = kk * 16 + (g & 1) * 8;
                uint32_t r[4];
                ldsm_x4(r, b_base + (uint32_t)(row * LDSTR + col) * 2);
                bfr[2 * p][0] = r[0];     bfr[2 * p][1] = r[1];
                bfr[2 * p + 1][0] = r[2]; bfr[2 * p + 1][1] = r[3];
            }
            #pragma unroll
            for (int mt = 0; mt < 2; mt++)
                #pragma unroll
                for (int nt = 0; nt < 8; nt++)
                    mma_bf16(acc[mt][nt], afr[mt], bfr[nt]);
        }
        __syncthreads();
    }

    // epilogue: direct stores with bias
    #pragma unroll
    for (int mt = 0; mt < 2; mt++) {
        #pragma unroll
        for (int nt = 0; nt < 8; nt++) {
            int row = m0 + wm + mt * 16 + (lane >> 2);
            int col = n0 + wn + nt * 8 + (lane & 3) * 2;
            if (col < nvalid) {
                float b0 = bias[col], b1 = bias[col + 1];
                float2 v0 = make_float2(acc[mt][nt][0] + b0, acc[mt][nt][1] + b1);
                float2 v1 = make_float2(acc[mt][nt][2] + b0, acc[mt][nt][3] + b1);
                *(float2*)(C + (size_t)row * ldc + col) = v0;
                *(float2*)(C + (size_t)(row + 8) * ldc + col) = v1;
            }
        }
    }
}

// ======================= weight conversion (fp32 -> bf16x3, transposed) =====
// W[K,N] -> Bo[N, 3K] rows: [hi | hi | lo]
__global__ void wconv_k(const float* __restrict__ W, __nv_bfloat16* __restrict__ Bo,
                        int N, int K) {
    int gi = blockIdx.x * 256 + threadIdx.x;
    if (gi >= N * (K >> 3)) return;
    int n = gi % N;
    int k0 = (gi / N) * 8;
    __align__(16) __nv_bfloat16 hi[8], lo[8];
    #pragma unroll
    for (int i = 0; i < 8; i++) {
        float w = W[(size_t)(k0 + i) * N + n];
        split_bf16(w, hi[i], lo[i]);
    }
    size_t base = (size_t)n * 3 * K;
    *(uint4*)(Bo + base + k0)         = *(uint4*)hi;
    *(uint4*)(Bo + base + K + k0)     = *(uint4*)hi;
    *(uint4*)(Bo + base + 2 * K + k0) = *(uint4*)lo;
}

// combined bc_w(2048x32) + dtr_w(2048x64) -> gB_bc[128, 3*2048]
__global__ void wbc_k(const float* __restrict__ bcw, const float* __restrict__ dtw,
                      __nv_bfloat16* __restrict__ Bo) {
    int gi = blockIdx.x * 256 + threadIdx.x;
    int n = gi % 128;
    int k0 = (gi / 128) * 8;
    __align__(16) __nv_bfloat16 hi[8], lo[8];
    #pragma unroll
    for (int i = 0; i < 8; i++) {
        int k = k0 + i;
        float w = 0.f;
        if (n < 32)      w = bcw[(size_t)k * 32 + n];
        else if (n < 96) w = dtw[(size_t)k * 64 + (n - 32)];
        split_bf16(w, hi[i], lo[i]);
    }
    size_t base = (size_t)n * 3 * INNER;
    *(uint4*)(Bo + base + k0)             = *(uint4*)hi;
    *(uint4*)(Bo + base + INNER + k0)     = *(uint4*)hi;
    *(uint4*)(Bo + base + 2 * INNER + k0) = *(uint4*)lo;
}

__global__ void bias96_k(const float* __restrict__ bcb, const float* __restrict__ dtrb,
                         float* __restrict__ out) {
    int j = threadIdx.x;
    if (j < 32) out[j] = bcb[j];
    else if (j < 96) out[j] = dtrb[j - 32];
}

// dtr slice of g_bcdtr -> gA_dtr [t, 3*64] rows: [hi | lo | hi]
__global__ void dtr_a3_k(const float* __restrict__ bcdtr, __nv_bfloat16* __restrict__ Ao) {
    int gi = blockIdx.x * 256 + threadIdx.x;
    int t = gi >> 6, j = gi & 63;
    float v = bcdtr[(size_t)t * 96 + 32 + j];
    __nv_bfloat16 h, l;
    split_bf16(v, h, l);
    size_t base = (size_t)t * 192;
    Ao[base + j] = h; Ao[base + 64 + j] = l; Ao[base + 128 + j] = h;
}

// ======================= LayerNorm -> A' (bf16x3) ===========================
__global__ void layernorm_a3_k(const float* __restrict__ x,
                               const float* __restrict__ w,
                               const float* __restrict__ b,
                               __nv_bfloat16* __restrict__ Ao) {
    int row = blockIdx.x;
    const float* xr = x + (size_t)row * H;
    float s = 0.f, s2 = 0.f;
    for (int i = threadIdx.x; i < H; i += 256) {
        float v = xr[i];
        s += v; s2 += v * v;
    }
    #pragma unroll
    for (int o = 16; o > 0; o >>= 1) {
        s  += __shfl_down_sync(0xffffffffu, s,  o);
        s2 += __shfl_down_sync(0xffffffffu, s2, o);
    }
    __shared__ float rs[8], rs2[8], stat[2];
    int wid = threadIdx.x >> 5, lid = threadIdx.x & 31;
    if (lid == 0) { rs[wid] = s; rs2[wid] = s2; }
    __syncthreads();
    if (threadIdx.x == 0) {
        float a = 0.f, c = 0.f;
        #pragma unroll
        for (int i = 0; i < 8; i++) { a += rs[i]; c += rs2[i]; }
        float mu = a / (float)H;
        stat[0] = mu;
        stat[1] = rsqrtf(c / (float)H - mu * mu + 1e-5f);
    }
    __syncthreads();
    float mu = stat[0], rstd = stat[1];
    size_t base = (size_t)row * 3 * H;
    for (int i = threadIdx.x; i < H; i += 256) {
        float v = (xr[i] - mu) * rstd * w[i] + b[i];
        __nv_bfloat16 h, l;
        split_bf16(v, h, l);
        Ao[base + i] = h; Ao[base + H + i] = l; Ao[base + 2 * H + i] = h;
    }
}

// ======================= conv(4-tap)+SiLU -> xa fp32 + A' bf16x3 ============
__global__ void conv_silu_a3_k(const float* __restrict__ xz,
                               const float* __restrict__ cw,
                               const float* __restrict__ cb,
                               float* __restrict__ xa,
                               __nv_bfloat16* __restrict__ Ao) {
    int idx = blockIdx.x * 256 + threadIdx.x;
    int d = idx & (INNER - 1);
    int tg = idx >> 11;
    int b = tg >> 10;
    int t = tg & (SEQ - 1);
    float4 w4 = *(const float4*)(cw + d * 4);
    float wv[4] = {w4.x, w4.y, w4.z, w4.w};
    float acc = cb[d];
    #pragma unroll
    for (int k = 0; k < 4; k++) {
        int tt = t - 3 + k;
        if (tt >= 0)
            acc = fmaf(xz[((size_t)(b * SEQ + tt)) * (2 * INNER) + d], wv[k], acc);
    }
    float s = acc / (1.f + __expf(-acc));
    xa[idx] = s;
    __nv_bfloat16 h, l;
    split_bf16(s, h, l);
    size_t base = (size_t)tg * (3 * INNER);
    Ao[base + d] = h; Ao[base + INNER + d] = l; Ao[base + 2 * INNER + d] = h;
}

// ======================= softplus + clip + mean =============================
__global__ void softplus_mean_k(float* __restrict__ dt, float* __restrict__ dtmean) {
    int t = blockIdx.x;
    float s = 0.f;
    for (int i = threadIdx.x; i < INNER; i += 256) {
        float v = dt[(size_t)t * INNER + i];
        float sp = (v > 20.f) ? v : log1pf(__expf(v));
        sp = fminf(fmaxf(sp, 0.001f), 0.1f);
        dt[(size_t)t * INNER + i] = sp;
        s += sp;
    }
    #pragma unroll
    for (int o = 16; o > 0; o >>= 1)
        s += __shfl_down_sync(0xffffffffu, s, o);
    __shared__ float rs[8];
    int wid = threadIdx.x >> 5, lid = threadIdx.x & 31;
    if (lid == 0) rs[wid] = s;
    __syncthreads();
    if (threadIdx.x == 0) {
        float a = 0.f;
        #pragma unroll
        for (int i = 0; i < 8; i++) a += rs[i];
        dtmean[t] = a / (float)INNER;
    }
}

// ======================= selective scan + gating -> A' (bf16x3) =============
__global__ void scan_k(const float* __restrict__ dt,
                       const float* __restrict__ xa,
                       const float* __restrict__ dtmean,
                       const float* __restrict__ bcdtr,
                       const float* __restrict__ xz,
                       __nv_bfloat16* __restrict__ Ao) {
    int b = blockIdx.y;
    int d = blockIdx.x * 64 + threadIdx.x;
    __shared__ float sBC[64 * 32];
    __shared__ float sDM[64];

    float h[16];
    #pragma unroll
    for (int n = 0; n < 16; n++) h[n] = 0.f;

    int base = b * SEQ;
    for (int tc = 0; tc < SEQ; tc += 64) {
        __syncthreads();
        for (int i = threadIdx.x; i < 64 * 32; i += 64)
            sBC[i] = bcdtr[(size_t)(base + tc + (i >> 5)) * 96 + (i & 31)];
        sDM[threadIdx.x] = dtmean[base + tc + threadIdx.x];
        __syncthreads();

        #pragma unroll 4
        for (int tt = 0; tt < 64; tt++) {
            int t = base + tc + tt;
            float dtv = dt[(size_t)t * INNER + d];
            float xav = xa[(size_t)t * INNER + d];
            float zv  = xz[(size_t)t * (2 * INNER) + INNER + d];

            float e1 = __expf(-dtv);
            float e2 = e1 * e1, e4 = e2 * e2, e8 = e4 * e4;
            float e3 = e2 * e1, e5 = e4 * e1, e6 = e4 * e2, e7 = e4 * e3;
            float ab[16] = {e1, e2, e3, e4, e5, e6, e7, e8,
                            e8 * e1, e8 * e2, e8 * e3, e8 * e4,
                            e8 * e5, e8 * e6, e8 * e7, e8 * e8};

            float bxv = sDM[tt] * xav;
            const float* Bm = &sBC[tt * 32];
            const float* Cm = Bm + 16;

            float y0 = 0.f, y1 = 0.f, y2 = 0.f, y3 = 0.f;
            #pragma unroll
            for (int n = 0; n < 16; n += 4) {
                h[n + 0] = fmaf(ab[n + 0], h[n + 0], bxv * Bm[n + 0]);
                h[n + 1] = fmaf(ab[n + 1], h[n + 1], bxv * Bm[n + 1]);
                h[n + 2] = fmaf(ab[n + 2], h[n + 2], bxv * Bm[n + 2]);
                h[n + 3] = fmaf(ab[n + 3], h[n + 3], bxv * Bm[n + 3]);
                y0 = fmaf(h[n + 0], Cm[n + 0], y0);
                y1 = fmaf(h[n + 1], Cm[n + 1], y1);
                y2 = fmaf(h[n + 2], Cm[n + 2], y2);
                y3 = fmaf(h[n + 3], Cm[n + 3], y3);
            }
            float y = (y0 + y1) + (y2 + y3);
            float sz = zv / (1.f + __expf(-zv));
            float g = y * sz;
            __nv_bfloat16 hh, ll;
            split_bf16(g, hh, ll);
            size_t ob = (size_t)t * (3 * INNER);
            Ao[ob + d] = hh; Ao[ob + INNER + d] = ll; Ao[ob + 2 * INNER + d] = hh;
        }
    }
}

// ======================= launch =============================================
extern "C" void kernel_launch(void* const* d_in, const int* in_sizes, int n_in,
                              void* d_out, int out_size) {
    const float* x      = (const float*)d_in[0];
    const float* norm_w = (const float*)d_in[1];
    const float* norm_b = (const float*)d_in[2];
    const float* in_w   = (const float*)d_in[3];
    const float* in_b   = (const float*)d_in[4];
    const float* conv_w = (const float*)d_in[5];
    const float* conv_b = (const float*)d_in[6];
    const float* bc_w   = (const float*)d_in[7];
    const float* bc_b   = (const float*)d_in[8];
    const float* dtr_w  = (const float*)d_in[9];
    const float* dtr_b  = (const float*)d_in[10];
    const float* dt_w   = (const float*)d_in[11];
    const float* dt_b   = (const float*)d_in[12];
    const float* out_w  = (const float*)d_in[13];
    const float* out_b  = (const float*)d_in[14];
    float* out = (float*)d_out;

    __nv_bfloat16 *pA_in, *pB_in, *pA_xa, *pB_bc, *pA_dtr, *pB_dt, *pA_out, *pB_out;
    float *pxz, *pxa, *pbcdtr, *pbias96, *pdt, *pdtm;
    cudaGetSymbolAddress((void**)&pA_in,  gA_in);
    cudaGetSymbolAddress((void**)&pB_in,  gB_in);
    cudaGetSymbolAddress((void**)&pxz,    g_xz);
    cudaGetSymbolAddress((void**)&pxa,    g_xa);
    cudaGetSymbolAddress((void**)&pA_xa,  gA_xa);
    cudaGetSymbolAddress((void**)&pB_bc,  gB_bc);
    cudaGetSymbolAddress((void**)&pbcdtr, g_bcdtr);
    cudaGetSymbolAddress((void**)&pbias96,g_bias96);
    cudaGetSymbolAddress((void**)&pA_dtr, gA_dtr);
    cudaGetSymbolAddress((void**)&pB_dt,  gB_dt);
    cudaGetSymbolAddress((void**)&pdt,    g_dt);
    cudaGetSymbolAddress((void**)&pdtm,   g_dtmean);
    cudaGetSymbolAddress((void**)&pA_out, gA_out);
    cudaGetSymbolAddress((void**)&pB_out, gB_out);

    const int DSMEM = 2 * BUFE * 2;  // 73728 bytes
    cudaFuncSetAttribute(gemm3_k, cudaFuncAttributeMaxDynamicSharedMemorySize, DSMEM);

    // weight conversions (independent of data path)
    wconv_k<<<(2 * INNER) * (H / 8) / 256, 256>>>(in_w, pB_in, 2 * INNER, H);
    wbc_k<<<128 * (INNER / 8) / 256, 256>>>(bc_w, dtr_w, pB_bc);
    bias96_k<<<1, 128>>>(bc_b, dtr_b, pbias96);
    wconv_k<<<INNER * (DTR / 8) / 256, 256>>>(dt_w, pB_dt, INNER, DTR);
    wconv_k<<<H * (INNER / 8) / 256, 256>>>(out_w, pB_out, H, INNER);

    // 1. LayerNorm -> A'
    layernorm_a3_k<<<TOK, 256>>>(x, norm_w, norm_b, pA_in);
    // 2. in-proj GEMM (M=2048, N=4096, K'=3072)
    gemm3_k<<<dim3(4096 / 128, TOK / 128), 256, DSMEM>>>(
        pA_in, pB_in, in_b, pxz, 3 * H, 2 * INNER, 2 * INNER);
    // 3. conv + SiLU -> xa + A'
    conv_silu_a3_k<<<(TOK * INNER) / 256, 256>>>(pxz, conv_w, conv_b, pxa, pA_xa);
    // 4. bc + dtr GEMM (M=2048, N=96 (pad 128), K'=6144)
    gemm3_k<<<dim3(1, TOK / 128), 256, DSMEM>>>(
        pA_xa, pB_bc, pbias96, pbcdtr, 3 * INNER, 96, 96);
    // 5. dtr -> A'
    dtr_a3_k<<<TOK * DTR / 256, 256>>>(pbcdtr, pA_dtr);
    // 6. dt GEMM (M=2048, N=2048, K'=192)
    gemm3_k<<<dim3(INNER / 128, TOK / 128), 256, DSMEM>>>(
        pA_dtr, pB_dt, dt_b, pdt, 3 * DTR, INNER, INNER);
    // 7. softplus + clip + mean
    softplus_mean_k<<<TOK, 256>>>(pdt, pdtm);
    // 8. scan + gating -> A'
    scan_k<<<dim3(INNER / 64, BATCH), 64>>>(pdt, pxa, pdtm, pbcdtr, pxz, pA_out);
    // 9. out-proj GEMM (M=2048, N=1024, K'=6144)
    gemm3_k<<<dim3(H / 128, TOK / 128), 256, DSMEM>>>(
        pA_out, pB_out, out_b, out, 3 * INNER, H, H);
}

// round 4
// speedup vs baseline: 2.6423x; 1.6949x over previous
#include <cuda_runtime.h>
#include <cuda_fp16.h>
#include <cstdint>
#include <math.h>

#define H      1024
#define INNER  2048
#define NST    16
#define DTR    64
#define BATCH  2
#define SEQ    1024
#define TOK    (BATCH*SEQ)   // 2048

// ======================= PTX helpers (plain sm_103 legal) ====================
__device__ __forceinline__ uint32_t smem_u32(const void* p) {
    uint32_t a;
    asm("{ .reg .u64 t; cvta.to.shared.u64 t, %1; cvt.u32.u64 %0, t; }"
        : "=r"(a) : "l"(p));
    return a;
}
__device__ __forceinline__ void cp16(uint32_t saddr, const void* g) {
    asm volatile("cp.async.cg.shared.global [%0], [%1], 16;"
                 :: "r"(saddr), "l"(g) : "memory");
}
#define CP_COMMIT() asm volatile("cp.async.commit_group;" ::: "memory")
#define CP_WAIT0()  asm volatile("cp.async.wait_group 0;" ::: "memory")

__device__ __forceinline__ void ldsm_x4(uint32_t* r, uint32_t addr) {
    asm volatile("ldmatrix.sync.aligned.m8n8.x4.shared.b16 {%0,%1,%2,%3}, [%4];"
                 : "=r"(r[0]), "=r"(r[1]), "=r"(r[2]), "=r"(r[3]) : "r"(addr));
}
__device__ __forceinline__ void mma_f16(float* c, const uint32_t* a, const uint32_t* b) {
    asm volatile("mma.sync.aligned.m16n8k16.row.col.f32.f16.f16.f32 "
                 "{%0,%1,%2,%3}, {%4,%5,%6,%7}, {%8,%9}, {%0,%1,%2,%3};"
                 : "+f"(c[0]), "+f"(c[1]), "+f"(c[2]), "+f"(c[3])
                 : "r"(a[0]), "r"(a[1]), "r"(a[2]), "r"(a[3]),
                   "r"(b[0]), "r"(b[1]));
}

// ======================= scratch buffers ====================================
__device__ __align__(16) __half gA_in [TOK * H];          // 4 MB
__device__ __align__(16) __half gB_in [2 * INNER * H];    // 8 MB
__device__ __align__(16) float  g_xz  [TOK * 2 * INNER];  // 33 MB
__device__ __align__(16) float  g_xa  [TOK * INNER];      // 16 MB
__device__ __align__(16) __half gA_xa [TOK * INNER];      // 8 MB
__device__ __align__(16) __half gB_bc [128 * INNER];      // 0.5 MB
__device__ __align__(16) float  g_bcdtr[TOK * 96];
__device__                float g_bias96[96];
__device__ __align__(16) __half gA_dtr[TOK * DTR];
__device__ __align__(16) __half gB_dt [INNER * DTR];
__device__ __align__(16) float  g_dt  [TOK * INNER];      // 16 MB
__device__                float g_dtmean[TOK];
__device__ __align__(16) __half gA_out[TOK * INNER];      // 8 MB
__device__ __align__(16) __half gB_out[H * INNER];        // 4 MB

// ======================= warp-MMA fp16 GEMM =================================
// C[M,N] = A[M,K]*B[N,K]^T + bias.  BM=BN=128, BK=64, 256 threads.
#define BM   128
#define BN   128
#define BKE  64
#define LDSTR 72                       // padded smem row stride in half
#define BUFE ((BM + BN) * LDSTR)       // elements per buffer

__global__ void __launch_bounds__(256)
gemm_h(const __half* __restrict__ A, const __half* __restrict__ B,
       const float* __restrict__ bias, float* __restrict__ C,
       int K, int ldc, int nvalid) {
    extern __shared__ __align__(16) __half sm[];
    const uint32_t smb = smem_u32(sm);

    const int tid = threadIdx.x;
    const int lane = tid & 31, wid = tid >> 5;
    const int m0 = blockIdx.y * BM, n0 = blockIdx.x * BN;
    const int wm = (wid & 3) * 32;       // warp row offset in tile
    const int wn = (wid >> 2) * 64;      // warp col offset in tile

    float acc[2][8][4];
    #pragma unroll
    for (int i = 0; i < 2; i++)
        #pragma unroll
        for (int j = 0; j < 8; j++)
            #pragma unroll
            for (int k = 0; k < 4; k++) acc[i][j][k] = 0.f;

    const int nc = K >> 6;

    auto load_tile = [&](int buf, int kc) {
        const __half* Ag = A + (size_t)m0 * K + kc * BKE;
        const __half* Bg = B + (size_t)n0 * K + kc * BKE;
        uint32_t sa = smb + buf * BUFE * 2;
        uint32_t sbb = sa + BM * LDSTR * 2;
        #pragma unroll
        for (int i = 0; i < 4; i++) {
            int ci = tid + i * 256;
            int row = ci >> 3, c8 = ci & 7;
            uint32_t so = (uint32_t)(row * LDSTR + c8 * 8) * 2;
            cp16(sa + so,  Ag + (size_t)row * K + c8 * 8);
            cp16(sbb + so, Bg + (size_t)row * K + c8 * 8);
        }
    };

    load_tile(0, 0);
    CP_COMMIT();

    for (int c = 0; c < nc; c++) {
        CP_WAIT0();
        __syncthreads();
        if (c + 1 < nc) { load_tile((c + 1) & 1, c + 1); CP_COMMIT(); }

        const int buf = c & 1;
        const uint32_t a_base = smb + buf * BUFE * 2;
        const uint32_t b_base = a_base + BM * LDSTR * 2;

        #pragma unroll
        for (int kk = 0; kk < 4; kk++) {
            uint32_t afr[2][4];
            #pragma unroll
            for (int mt = 0; mt < 2; mt++) {
                int row = wm + mt * 16 + (lane & 15);
                int col = kk * 16 + (lane >> 4) * 8;
                ldsm_x4(afr[mt], a_base + (uint32_t)(row * LDSTR + col) * 2);
            }
            uint32_t bfr[8][2];
            #pragma unroll
            for (int p = 0; p < 4; p++) {
                int g = lane >> 3, idx = lane & 7;
                int row = wn + p * 16 + idx + (g >> 1) * 8;
                int col = kk * 16 + (g & 1) * 8;
                uint32_t r[4];
                ldsm_x4(r, b_base + (uint32_t)(row * LDSTR + col) * 2);
                bfr[2 * p][0] = r[0];     bfr[2 * p][1] = r[1];
                bfr[2 * p + 1][0] = r[2]; bfr[2 * p + 1][1] = r[3];
            }
            #pragma unroll
            for (int mt = 0; mt < 2; mt++)
                #pragma unroll
                for (int nt = 0; nt < 8; nt++)
                    mma_f16(acc[mt][nt], afr[mt], bfr[nt]);
        }
        __syncthreads();
    }

    // epilogue: direct stores with bias
    #pragma unroll
    for (int mt = 0; mt < 2; mt++) {
        #pragma unroll
        for (int nt = 0; nt < 8; nt++) {
            int row = m0 + wm + mt * 16 + (lane >> 2);
            int col = n0 + wn + nt * 8 + (lane & 3) * 2;
            if (col < nvalid) {
                float b0 = bias[col], b1 = bias[col + 1];
                float2 v0 = make_float2(acc[mt][nt][0] + b0, acc[mt][nt][1] + b1);
                float2 v1 = make_float2(acc[mt][nt][2] + b0, acc[mt][nt][3] + b1);
                *(float2*)(C + (size_t)row * ldc + col) = v0;
                *(float2*)(C + (size_t)(row + 8) * ldc + col) = v1;
            }
        }
    }
}

// ======================= weight conversion (fp32 -> fp16, transposed) =======
// W[K,N] -> Bo[N, K]
__global__ void wconv_k(const float* __restrict__ W, __half* __restrict__ Bo,
                        int N, int K) {
    int gi = blockIdx.x * 256 + threadIdx.x;
    if (gi >= N * (K >> 3)) return;
    int n = gi % N;
    int k0 = (gi / N) * 8;
    __align__(16) __half hv[8];
    #pragma unroll
    for (int i = 0; i < 8; i++)
        hv[i] = __float2half(W[(size_t)(k0 + i) * N + n]);
    *(uint4*)(Bo + (size_t)n * K + k0) = *(uint4*)hv;
}

// combined bc_w(2048x32) + dtr_w(2048x64) -> gB_bc[128, 2048]
__global__ void wbc_k(const float* __restrict__ bcw, const float* __restrict__ dtw,
                      __half* __restrict__ Bo) {
    int gi = blockIdx.x * 256 + threadIdx.x;
    int n = gi % 128;
    int k0 = (gi / 128) * 8;
    __align__(16) __half hv[8];
    #pragma unroll
    for (int i = 0; i < 8; i++) {
        int k = k0 + i;
        float w = 0.f;
        if (n < 32)      w = bcw[(size_t)k * 32 + n];
        else if (n < 96) w = dtw[(size_t)k * 64 + (n - 32)];
        hv[i] = __float2half(w);
    }
    *(uint4*)(Bo + (size_t)n * INNER + k0) = *(uint4*)hv;
}

__global__ void bias96_k(const float* __restrict__ bcb, const float* __restrict__ dtrb,
                         float* __restrict__ out) {
    int j = threadIdx.x;
    if (j < 32) out[j] = bcb[j];
    else if (j < 96) out[j] = dtrb[j - 32];
}

// dtr slice of g_bcdtr -> gA_dtr [t, 64] fp16
__global__ void dtr_h_k(const float* __restrict__ bcdtr, __half* __restrict__ Ao) {
    int gi = blockIdx.x * 256 + threadIdx.x;
    int t = gi >> 6, j = gi & 63;
    Ao[(size_t)t * 64 + j] = __float2half(bcdtr[(size_t)t * 96 + 32 + j]);
}

// ======================= LayerNorm -> fp16 A ================================
__global__ void layernorm_h_k(const float* __restrict__ x,
                              const float* __restrict__ w,
                              const float* __restrict__ b,
                              __half* __restrict__ Ao) {
    int row = blockIdx.x;
    const float* xr = x + (size_t)row * H;
    float s = 0.f, s2 = 0.f;
    for (int i = threadIdx.x; i < H; i += 256) {
        float v = xr[i];
        s += v; s2 += v * v;
    }
    #pragma unroll
    for (int o = 16; o > 0; o >>= 1) {
        s  += __shfl_down_sync(0xffffffffu, s,  o);
        s2 += __shfl_down_sync(0xffffffffu, s2, o);
    }
    __shared__ float rs[8], rs2[8], stat[2];
    int wid = threadIdx.x >> 5, lid = threadIdx.x & 31;
    if (lid == 0) { rs[wid] = s; rs2[wid] = s2; }
    __syncthreads();
    if (threadIdx.x == 0) {
        float a = 0.f, c = 0.f;
        #pragma unroll
        for (int i = 0; i < 8; i++) { a += rs[i]; c += rs2[i]; }
        float mu = a / (float)H;
        stat[0] = mu;
        stat[1] = rsqrtf(c / (float)H - mu * mu + 1e-5f);
    }
    __syncthreads();
    float mu = stat[0], rstd = stat[1];
    for (int i = threadIdx.x; i < H; i += 256)
        Ao[(size_t)row * H + i] = __float2half((xr[i] - mu) * rstd * w[i] + b[i]);
}

// ======================= conv(4-tap)+SiLU -> xa fp32 + fp16 A ===============
__global__ void conv_silu_h_k(const float* __restrict__ xz,
                              const float* __restrict__ cw,
                              const float* __restrict__ cb,
                              float* __restrict__ xa,
                              __half* __restrict__ Ao) {
    int idx = blockIdx.x * 256 + threadIdx.x;
    int d = idx & (INNER - 1);
    int tg = idx >> 11;
    int b = tg >> 10;
    int t = tg & (SEQ - 1);
    float4 w4 = *(const float4*)(cw + d * 4);
    float wv[4] = {w4.x, w4.y, w4.z, w4.w};
    float acc = cb[d];
    #pragma unroll
    for (int k = 0; k < 4; k++) {
        int tt = t - 3 + k;
        if (tt >= 0)
            acc = fmaf(xz[((size_t)(b * SEQ + tt)) * (2 * INNER) + d], wv[k], acc);
    }
    float s = acc / (1.f + __expf(-acc));
    xa[idx] = s;
    Ao[idx] = __float2half(s);
}

// ======================= softplus + clip + mean =============================
__global__ void softplus_mean_k(float* __restrict__ dt, float* __restrict__ dtmean) {
    int t = blockIdx.x;
    float s = 0.f;
    for (int i = threadIdx.x; i < INNER; i += 256) {
        float v = dt[(size_t)t * INNER + i];
        float sp = (v > 20.f) ? v : log1pf(__expf(v));
        sp = fminf(fmaxf(sp, 0.001f), 0.1f);
        dt[(size_t)t * INNER + i] = sp;
        s += sp;
    }
    #pragma unroll
    for (int o = 16; o > 0; o >>= 1)
        s += __shfl_down_sync(0xffffffffu, s, o);
    __shared__ float rs[8];
    int wid = threadIdx.x >> 5, lid = threadIdx.x & 31;
    if (lid == 0) rs[wid] = s;
    __syncthreads();
    if (threadIdx.x == 0) {
        float a = 0.f;
        #pragma unroll
        for (int i = 0; i < 8; i++) a += rs[i];
        dtmean[t] = a / (float)INNER;
    }
}

// ======================= selective scan + gating -> fp16 A ==================
// grid (INNER/64, BATCH), block 64. Prefetch t+1 operands while computing t.
__global__ void scan_k(const float* __restrict__ dt,
                       const float* __restrict__ xa,
                       const float* __restrict__ dtmean,
                       const float* __restrict__ bcdtr,
                       const float* __restrict__ xz,
                       __half* __restrict__ Ao) {
    int b = blockIdx.y;
    int d = blockIdx.x * 64 + threadIdx.x;
    __shared__ float sBC[64 * 32];
    __shared__ float sDM[64];

    float h[16];
    #pragma unroll
    for (int n = 0; n < 16; n++) h[n] = 0.f;

    const int base = b * SEQ;
    // preload t = 0
    float dtv = dt[(size_t)base * INNER + d];
    float xav = xa[(size_t)base * INNER + d];
    float zv  = xz[(size_t)base * (2 * INNER) + INNER + d];

    for (int tc = 0; tc < SEQ; tc += 64) {
        __syncthreads();
        for (int i = threadIdx.x; i < 64 * 32; i += 64)
            sBC[i] = bcdtr[(size_t)(base + tc + (i >> 5)) * 96 + (i & 31)];
        sDM[threadIdx.x] = dtmean[base + tc + threadIdx.x];
        __syncthreads();

        #pragma unroll 4
        for (int tt = 0; tt < 64; tt++) {
            const int t = base + tc + tt;
            // prefetch next token's operands (clamped at sequence end)
            const int tn = (tc + tt + 1 < SEQ) ? t + 1 : t;
            float dtv_n = dt[(size_t)tn * INNER + d];
            float xav_n = xa[(size_t)tn * INNER + d];
            float zv_n  = xz[(size_t)tn * (2 * INNER) + INNER + d];

            float e1 = __expf(-dtv);
            float e2 = e1 * e1, e4 = e2 * e2, e8 = e4 * e4;
            float e3 = e2 * e1, e5 = e4 * e1, e6 = e4 * e2, e7 = e4 * e3;
            float ab[16] = {e1, e2, e3, e4, e5, e6, e7, e8,
                            e8 * e1, e8 * e2, e8 * e3, e8 * e4,
                            e8 * e5, e8 * e6, e8 * e7, e8 * e8};

            float bxv = sDM[tt] * xav;
            const float* Bm = &sBC[tt * 32];
            const float* Cm = Bm + 16;

            float y0 = 0.f, y1 = 0.f, y2 = 0.f, y3 = 0.f;
            #pragma unroll
            for (int n = 0; n < 16; n += 4) {
                h[n + 0] = fmaf(ab[n + 0], h[n + 0], bxv * Bm[n + 0]);
                h[n + 1] = fmaf(ab[n + 1], h[n + 1], bxv * Bm[n + 1]);
                h[n + 2] = fmaf(ab[n + 2], h[n + 2], bxv * Bm[n + 2]);
                h[n + 3] = fmaf(ab[n + 3], h[n + 3], bxv * Bm[n + 3]);
                y0 = fmaf(h[n + 0], Cm[n + 0], y0);
                y1 = fmaf(h[n + 1], Cm[n + 1], y1);
                y2 = fmaf(h[n + 2], Cm[n + 2], y2);
                y3 = fmaf(h[n + 3], Cm[n + 3], y3);
            }
            float y = (y0 + y1) + (y2 + y3);
            float sz = zv / (1.f + __expf(-zv));
            Ao[(size_t)t * INNER + d] = __float2half(y * sz);

            dtv = dtv_n; xav = xav_n; zv = zv_n;
        }
    }
}

// ======================= launch =============================================
extern "C" void kernel_launch(void* const* d_in, const int* in_sizes, int n_in,
                              void* d_out, int out_size) {
    const float* x      = (const float*)d_in[0];
    const float* norm_w = (const float*)d_in[1];
    const float* norm_b = (const float*)d_in[2];
    const float* in_w   = (const float*)d_in[3];
    const float* in_b   = (const float*)d_in[4];
    const float* conv_w = (const float*)d_in[5];
    const float* conv_b = (const float*)d_in[6];
    const float* bc_w   = (const float*)d_in[7];
    const float* bc_b   = (const float*)d_in[8];
    const float* dtr_w  = (const float*)d_in[9];
    const float* dtr_b  = (const float*)d_in[10];
    const float* dt_w   = (const float*)d_in[11];
    const float* dt_b   = (const float*)d_in[12];
    const float* out_w  = (const float*)d_in[13];
    const float* out_b  = (const float*)d_in[14];
    float* out = (float*)d_out;

    __half *pA_in, *pB_in, *pA_xa, *pB_bc, *pA_dtr, *pB_dt, *pA_out, *pB_out;
    float *pxz, *pxa, *pbcdtr, *pbias96, *pdt, *pdtm;
    cudaGetSymbolAddress((void**)&pA_in,  gA_in);
    cudaGetSymbolAddress((void**)&pB_in,  gB_in);
    cudaGetSymbolAddress((void**)&pxz,    g_xz);
    cudaGetSymbolAddress((void**)&pxa,    g_xa);
    cudaGetSymbolAddress((void**)&pA_xa,  gA_xa);
    cudaGetSymbolAddress((void**)&pB_bc,  gB_bc);
    cudaGetSymbolAddress((void**)&pbcdtr, g_bcdtr);
    cudaGetSymbolAddress((void**)&pbias96,g_bias96);
    cudaGetSymbolAddress((void**)&pA_dtr, gA_dtr);
    cudaGetSymbolAddress((void**)&pB_dt,  gB_dt);
    cudaGetSymbolAddress((void**)&pdt,    g_dt);
    cudaGetSymbolAddress((void**)&pdtm,   g_dtmean);
    cudaGetSymbolAddress((void**)&pA_out, gA_out);
    cudaGetSymbolAddress((void**)&pB_out, gB_out);

    const int DSMEM = 2 * BUFE * 2;  // 73728 bytes
    cudaFuncSetAttribute(gemm_h, cudaFuncAttributeMaxDynamicSharedMemorySize, DSMEM);

    // weight conversions (independent of data path)
    wconv_k<<<(2 * INNER) * (H / 8) / 256, 256>>>(in_w, pB_in, 2 * INNER, H);
    wbc_k<<<128 * (INNER / 8) / 256, 256>>>(bc_w, dtr_w, pB_bc);
    bias96_k<<<1, 128>>>(bc_b, dtr_b, pbias96);
    wconv_k<<<INNER * (DTR / 8) / 256, 256>>>(dt_w, pB_dt, INNER, DTR);
    wconv_k<<<H * (INNER / 8) / 256, 256>>>(out_w, pB_out, H, INNER);

    // 1. LayerNorm -> fp16 A
    layernorm_h_k<<<TOK, 256>>>(x, norm_w, norm_b, pA_in);
    // 2. in-proj GEMM (M=2048, N=4096, K=1024)
    gemm_h<<<dim3(4096 / 128, TOK / 128), 256, DSMEM>>>(
        pA_in, pB_in, in_b, pxz, H, 2 * INNER, 2 * INNER);
    // 3. conv + SiLU -> xa fp32 + fp16 A
    conv_silu_h_k<<<(TOK * INNER) / 256, 256>>>(pxz, conv_w, conv_b, pxa, pA_xa);
    // 4. bc + dtr GEMM (M=2048, N=96 (pad 128), K=2048)
    gemm_h<<<dim3(1, TOK / 128), 256, DSMEM>>>(
        pA_xa, pB_bc, pbias96, pbcdtr, INNER, 96, 96);
    // 5. dtr -> fp16 A
    dtr_h_k<<<TOK * DTR / 256, 256>>>(pbcdtr, pA_dtr);
    // 6. dt GEMM (M=2048, N=2048, K=64)
    gemm_h<<<dim3(INNER / 128, TOK / 128), 256, DSMEM>>>(
        pA_dtr, pB_dt, dt_b, pdt, DTR, INNER, INNER);
    // 7. softplus + clip + mean
    softplus_mean_k<<<TOK, 256>>>(pdt, pdtm);
    // 8. scan + gating -> fp16 A
    scan_k<<<dim3(INNER / 64, BATCH), 64>>>(pdt, pxa, pdtm, pbcdtr, pxz, pA_out);
    // 9. out-proj GEMM (M=2048, N=1024, K=2048)
    gemm_h<<<dim3(H / 128, TOK / 128), 256, DSMEM>>>(
        pA_out, pB_out, out_b, out, INNER, H, H);
}

// round 5
// speedup vs baseline: 3.0259x; 1.1452x over previous
#include <cuda_runtime.h>
#include <cuda_fp16.h>
#include <cstdint>
#include <math.h>

#define H      1024
#define INNER  2048
#define NST    16
#define DTR    64
#define BATCH  2
#define SEQ    1024
#define TOK    (BATCH*SEQ)   // 2048

// ======================= PTX helpers (plain sm_103 legal) ====================
__device__ __forceinline__ uint32_t smem_u32(const void* p) {
    uint32_t a;
    asm("{ .reg .u64 t; cvta.to.shared.u64 t, %1; cvt.u32.u64 %0, t; }"
        : "=r"(a) : "l"(p));
    return a;
}
__device__ __forceinline__ void cp16(uint32_t saddr, const void* g) {
    asm volatile("cp.async.cg.shared.global [%0], [%1], 16;"
                 :: "r"(saddr), "l"(g) : "memory");
}
#define CP_COMMIT() asm volatile("cp.async.commit_group;" ::: "memory")
#define CP_WAIT0()  asm volatile("cp.async.wait_group 0;" ::: "memory")

__device__ __forceinline__ void ldsm_x4(uint32_t* r, uint32_t addr) {
    asm volatile("ldmatrix.sync.aligned.m8n8.x4.shared.b16 {%0,%1,%2,%3}, [%4];"
                 : "=r"(r[0]), "=r"(r[1]), "=r"(r[2]), "=r"(r[3]) : "r"(addr));
}
__device__ __forceinline__ void mma_f16(float* c, const uint32_t* a, const uint32_t* b) {
    asm volatile("mma.sync.aligned.m16n8k16.row.col.f32.f16.f16.f32 "
                 "{%0,%1,%2,%3}, {%4,%5,%6,%7}, {%8,%9}, {%0,%1,%2,%3};"
                 : "+f"(c[0]), "+f"(c[1]), "+f"(c[2]), "+f"(c[3])
                 : "r"(a[0]), "r"(a[1]), "r"(a[2]), "r"(a[3]),
                   "r"(b[0]), "r"(b[1]));
}

// ======================= scratch buffers ====================================
__device__ __align__(16) __half gA_in [TOK * H];
__device__ __align__(16) __half gB_in [2 * INNER * H];
__device__ __align__(16) float  g_xz  [TOK * 2 * INNER];
__device__ __align__(16) float  g_xa  [TOK * INNER];
__device__ __align__(16) float  g_bcdtr[TOK * 96];
__device__ __align__(16) __half gA_dtr[TOK * DTR];
__device__ __align__(16) __half gB_dt [INNER * DTR];
__device__ __align__(16) float  g_dt  [TOK * INNER];
__device__                float g_dtmean[TOK];
__device__ __align__(16) __half gA_out[TOK * INNER];
__device__ __align__(16) __half gB_out[H * INNER];

// ======================= warp-MMA fp16 GEMM =================================
// C[M,N] = A[M,K]*B[N,K]^T + bias.  BM=BN=128, BK=64, 256 threads.
// EPI = 0: plain; EPI = 1: softplus+clip (dt path).
#define BM   128
#define BN   128
#define BKE  64
#define LDSTR 72
#define BUFE ((BM + BN) * LDSTR)

template <int EPI>
__global__ void __launch_bounds__(256)
gemm_h(const __half* __restrict__ A, const __half* __restrict__ B,
       const float* __restrict__ bias, float* __restrict__ C,
       int K, int ldc, int nvalid) {
    extern __shared__ __align__(16) __half sm[];
    const uint32_t smb = smem_u32(sm);

    const int tid = threadIdx.x;
    const int lane = tid & 31, wid = tid >> 5;
    const int m0 = blockIdx.y * BM, n0 = blockIdx.x * BN;
    const int wm = (wid & 3) * 32;
    const int wn = (wid >> 2) * 64;

    float acc[2][8][4];
    #pragma unroll
    for (int i = 0; i < 2; i++)
        #pragma unroll
        for (int j = 0; j < 8; j++)
            #pragma unroll
            for (int k = 0; k < 4; k++) acc[i][j][k] = 0.f;

    const int nc = K >> 6;

    auto load_tile = [&](int buf, int kc) {
        const __half* Ag = A + (size_t)m0 * K + kc * BKE;
        const __half* Bg = B + (size_t)n0 * K + kc * BKE;
        uint32_t sa = smb + buf * BUFE * 2;
        uint32_t sbb = sa + BM * LDSTR * 2;
        #pragma unroll
        for (int i = 0; i < 4; i++) {
            int ci = tid + i * 256;
            int row = ci >> 3, c8 = ci & 7;
            uint32_t so = (uint32_t)(row * LDSTR + c8 * 8) * 2;
            cp16(sa + so,  Ag + (size_t)row * K + c8 * 8);
            cp16(sbb + so, Bg + (size_t)row * K + c8 * 8);
        }
    };

    load_tile(0, 0);
    CP_COMMIT();

    for (int c = 0; c < nc; c++) {
        CP_WAIT0();
        __syncthreads();
        if (c + 1 < nc) { load_tile((c + 1) & 1, c + 1); CP_COMMIT(); }

        const int buf = c & 1;
        const uint32_t a_base = smb + buf * BUFE * 2;
        const uint32_t b_base = a_base + BM * LDSTR * 2;

        #pragma unroll
        for (int kk = 0; kk < 4; kk++) {
            uint32_t afr[2][4];
            #pragma unroll
            for (int mt = 0; mt < 2; mt++) {
                int row = wm + mt * 16 + (lane & 15);
                int col = kk * 16 + (lane >> 4) * 8;
                ldsm_x4(afr[mt], a_base + (uint32_t)(row * LDSTR + col) * 2);
            }
            uint32_t bfr[8][2];
            #pragma unroll
            for (int p = 0; p < 4; p++) {
                int g = lane >> 3, idx = lane & 7;
                int row = wn + p * 16 + idx + (g >> 1) * 8;
                int col = kk * 16 + (g & 1) * 8;
                uint32_t r[4];
                ldsm_x4(r, b_base + (uint32_t)(row * LDSTR + col) * 2);
                bfr[2 * p][0] = r[0];     bfr[2 * p][1] = r[1];
                bfr[2 * p + 1][0] = r[2]; bfr[2 * p + 1][1] = r[3];
            }
            #pragma unroll
            for (int mt = 0; mt < 2; mt++)
                #pragma unroll
                for (int nt = 0; nt < 8; nt++)
                    mma_f16(acc[mt][nt], afr[mt], bfr[nt]);
        }
        __syncthreads();
    }

    #pragma unroll
    for (int mt = 0; mt < 2; mt++) {
        #pragma unroll
        for (int nt = 0; nt < 8; nt++) {
            int row = m0 + wm + mt * 16 + (lane >> 2);
            int col = n0 + wn + nt * 8 + (lane & 3) * 2;
            if (col < nvalid) {
                float b0 = bias[col], b1 = bias[col + 1];
                float v00 = acc[mt][nt][0] + b0, v01 = acc[mt][nt][1] + b1;
                float v10 = acc[mt][nt][2] + b0, v11 = acc[mt][nt][3] + b1;
                if (EPI == 1) {
                    v00 = (v00 > 20.f) ? v00 : log1pf(__expf(v00));
                    v01 = (v01 > 20.f) ? v01 : log1pf(__expf(v01));
                    v10 = (v10 > 20.f) ? v10 : log1pf(__expf(v10));
                    v11 = (v11 > 20.f) ? v11 : log1pf(__expf(v11));
                    v00 = fminf(fmaxf(v00, 0.001f), 0.1f);
                    v01 = fminf(fmaxf(v01, 0.001f), 0.1f);
                    v10 = fminf(fmaxf(v10, 0.001f), 0.1f);
                    v11 = fminf(fmaxf(v11, 0.001f), 0.1f);
                }
                *(float2*)(C + (size_t)row * ldc + col) = make_float2(v00, v01);
                *(float2*)(C + (size_t)(row + 8) * ldc + col) = make_float2(v10, v11);
            }
        }
    }
}

// ======================= weight conversion (fp32 -> fp16, transposed) =======
__global__ void wconv_k(const float* __restrict__ W, __half* __restrict__ Bo,
                        int N, int K) {
    int gi = blockIdx.x * 256 + threadIdx.x;
    if (gi >= N * (K >> 3)) return;
    int n = gi % N;
    int k0 = (gi / N) * 8;
    __align__(16) __half hv[8];
    #pragma unroll
    for (int i = 0; i < 8; i++)
        hv[i] = __float2half(W[(size_t)(k0 + i) * N + n]);
    *(uint4*)(Bo + (size_t)n * K + k0) = *(uint4*)hv;
}

// ======================= fp32 bc+dtr projection ==============================
// bcdtr[t, 0:96] = xa[t,:] @ [bc_w | dtr_w] + [bc_b | dtr_b]
// block: 256 thr, 16 tokens x 96 cols; thread = (r = tid/16, jg = tid%16) -> 6 cols
__global__ void __launch_bounds__(256)
bcproj_k(const float* __restrict__ xa,
         const float* __restrict__ bcw, const float* __restrict__ dtw,
         const float* __restrict__ bcb, const float* __restrict__ dtrb,
         float* __restrict__ outp) {
    __shared__ float sW[64][100];
    __shared__ float sA[16][65];
    const int tid = threadIdx.x;
    const int r = tid >> 4, jg = tid & 15;
    const int m0 = blockIdx.x * 16;

    float acc[6];
    #pragma unroll
    for (int c = 0; c < 6; c++) acc[c] = 0.f;

    for (int k0 = 0; k0 < INNER; k0 += 64) {
        __syncthreads();
        for (int idx = tid; idx < 64 * 96; idx += 256) {
            int kl = idx / 96, j = idx % 96;
            float v = (j < 32) ? bcw[(size_t)(k0 + kl) * 32 + j]
                               : dtw[(size_t)(k0 + kl) * 64 + (j - 32)];
            sW[kl][j] = v;
        }
        for (int idx = tid; idx < 16 * 64; idx += 256) {
            int rr = idx >> 6, kl = idx & 63;
            sA[rr][kl] = xa[(size_t)(m0 + rr) * INNER + k0 + kl];
        }
        __syncthreads();
        #pragma unroll 8
        for (int kl = 0; kl < 64; kl++) {
            float a = sA[r][kl];
            const float* wrow = &sW[kl][jg * 6];
            float2 w01 = *(const float2*)(wrow);
            float2 w23 = *(const float2*)(wrow + 2);
            float2 w45 = *(const float2*)(wrow + 4);
            acc[0] = fmaf(a, w01.x, acc[0]);
            acc[1] = fmaf(a, w01.y, acc[1]);
            acc[2] = fmaf(a, w23.x, acc[2]);
            acc[3] = fmaf(a, w23.y, acc[3]);
            acc[4] = fmaf(a, w45.x, acc[4]);
            acc[5] = fmaf(a, w45.y, acc[5]);
        }
    }
    #pragma unroll
    for (int c = 0; c < 6; c++) {
        int j = jg * 6 + c;
        float bv = (j < 32) ? bcb[j] : dtrb[j - 32];
        outp[(size_t)(m0 + r) * 96 + j] = acc[c] + bv;
    }
}

// dtr slice of g_bcdtr -> gA_dtr [t, 64] fp16
__global__ void dtr_h_k(const float* __restrict__ bcdtr, __half* __restrict__ Ao) {
    int gi = blockIdx.x * 256 + threadIdx.x;
    int t = gi >> 6, j = gi & 63;
    Ao[(size_t)t * 64 + j] = __float2half(bcdtr[(size_t)t * 96 + 32 + j]);
}

// ======================= LayerNorm -> fp16 A ================================
__global__ void layernorm_h_k(const float* __restrict__ x,
                              const float* __restrict__ w,
                              const float* __restrict__ b,
                              __half* __restrict__ Ao) {
    int row = blockIdx.x;
    const float* xr = x + (size_t)row * H;
    float s = 0.f, s2 = 0.f;
    for (int i = threadIdx.x; i < H; i += 256) {
        float v = xr[i];
        s += v; s2 += v * v;
    }
    #pragma unroll
    for (int o = 16; o > 0; o >>= 1) {
        s  += __shfl_down_sync(0xffffffffu, s,  o);
        s2 += __shfl_down_sync(0xffffffffu, s2, o);
    }
    __shared__ float rs[8], rs2[8], stat[2];
    int wid = threadIdx.x >> 5, lid = threadIdx.x & 31;
    if (lid == 0) { rs[wid] = s; rs2[wid] = s2; }
    __syncthreads();
    if (threadIdx.x == 0) {
        float a = 0.f, c = 0.f;
        #pragma unroll
        for (int i = 0; i < 8; i++) { a += rs[i]; c += rs2[i]; }
        float mu = a / (float)H;
        stat[0] = mu;
        stat[1] = rsqrtf(c / (float)H - mu * mu + 1e-5f);
    }
    __syncthreads();
    float mu = stat[0], rstd = stat[1];
    for (int i = threadIdx.x; i < H; i += 256)
        Ao[(size_t)row * H + i] = __float2half((xr[i] - mu) * rstd * w[i] + b[i]);
}

// ======================= conv(4-tap)+SiLU -> xa fp32 ========================
__global__ void conv_silu_k(const float* __restrict__ xz,
                            const float* __restrict__ cw,
                            const float* __restrict__ cb,
                            float* __restrict__ xa) {
    int idx = blockIdx.x * 256 + threadIdx.x;
    int d = idx & (INNER - 1);
    int tg = idx >> 11;
    int b = tg >> 10;
    int t = tg & (SEQ - 1);
    float4 w4 = *(const float4*)(cw + d * 4);
    float wv[4] = {w4.x, w4.y, w4.z, w4.w};
    float acc = cb[d];
    #pragma unroll
    for (int k = 0; k < 4; k++) {
        int tt = t - 3 + k;
        if (tt >= 0)
            acc = fmaf(xz[((size_t)(b * SEQ + tt)) * (2 * INNER) + d], wv[k], acc);
    }
    xa[idx] = acc / (1.f + __expf(-acc));
}

// ======================= per-token mean of clipped dt ========================
__global__ void mean_k(const float* __restrict__ dt, float* __restrict__ m) {
    int t = blockIdx.x;
    float s = 0.f;
    for (int i = threadIdx.x; i < INNER; i += 256)
        s += dt[(size_t)t * INNER + i];
    #pragma unroll
    for (int o = 16; o > 0; o >>= 1)
        s += __shfl_down_sync(0xffffffffu, s, o);
    __shared__ float rs[8];
    int wid = threadIdx.x >> 5, lid = threadIdx.x & 31;
    if (lid == 0) rs[wid] = s;
    __syncthreads();
    if (threadIdx.x == 0) {
        float a = 0.f;
        #pragma unroll
        for (int i = 0; i < 8; i++) a += rs[i];
        m[t] = a / (float)INNER;
    }
}

// ======================= segmented parallel scan + gating ====================
// grid (INNER/32, BATCH), block 256 = 32 d-lanes x 8 segments of 128 steps.
#define SEGS   8
#define SEGLEN 128

__device__ __forceinline__ void pow_ladder(float e1, float* p) {
    float e2 = e1 * e1, e4 = e2 * e2, e8 = e4 * e4;
    p[0] = e1;       p[1] = e2;       p[2] = e2 * e1;  p[3] = e4;
    p[4] = e4 * e1;  p[5] = e4 * e2;  p[6] = e4 * p[2]; p[7] = e8;
    p[8] = e8 * e1;  p[9] = e8 * e2;  p[10] = e8 * p[2]; p[11] = e8 * e4;
    p[12] = e8 * p[4]; p[13] = e8 * p[5]; p[14] = e8 * p[6]; p[15] = e8 * e8;
}

__global__ void __launch_bounds__(256)
scan_k(const float* __restrict__ dt,
       const float* __restrict__ xa,
       const float* __restrict__ dtmean,
       const float* __restrict__ bcdtr,
       const float* __restrict__ xz,
       __half* __restrict__ Ao) {
    __shared__ float shH[SEGS][32][NST];
    __shared__ float shS[SEGS][32];

    const int tid = threadIdx.x;
    const int dlane = tid & 31, s = tid >> 5;
    const int b = blockIdx.y;
    const int d = blockIdx.x * 32 + dlane;
    const int t0 = b * SEQ + s * SEGLEN;

    // ---- sweep A: local scan from zero, accumulate sum(dt) ----
    float h[NST];
    #pragma unroll
    for (int n = 0; n < NST; n++) h[n] = 0.f;
    float sdt = 0.f;

    for (int i = 0; i < SEGLEN; i++) {
        const int t = t0 + i;
        float dtv = dt[(size_t)t * INNER + d];
        float xav = xa[(size_t)t * INNER + d];
        float dm  = dtmean[t];
        float bx  = dm * xav;
        sdt += dtv;
        float p[NST];
        pow_ladder(__expf(-dtv), p);
        const float4* bp = (const float4*)(bcdtr + (size_t)t * 96);
        float4 b0 = bp[0], b1 = bp[1], b2 = bp[2], b3 = bp[3];
        float Bm[NST] = {b0.x, b0.y, b0.z, b0.w, b1.x, b1.y, b1.z, b1.w,
                         b2.x, b2.y, b2.z, b2.w, b3.x, b3.y, b3.z, b3.w};
        #pragma unroll
        for (int n = 0; n < NST; n++)
            h[n] = fmaf(p[n], h[n], bx * Bm[n]);
    }
    shS[s][dlane] = sdt;
    #pragma unroll
    for (int n = 0; n < NST; n++) shH[s][dlane][n] = h[n];
    __syncthreads();

    // ---- combine: true initial state for this segment ----
    float hin[NST];
    #pragma unroll
    for (int n = 0; n < NST; n++) hin[n] = 0.f;
    for (int j = 0; j < s; j++) {
        float p[NST];
        pow_ladder(__expf(-shS[j][dlane]), p);
        #pragma unroll
        for (int n = 0; n < NST; n++)
            hin[n] = fmaf(p[n], hin[n], shH[j][dlane][n]);
    }

    // ---- sweep B: rescan with true initial state, emit gated output ----
    #pragma unroll
    for (int n = 0; n < NST; n++) h[n] = hin[n];

    for (int i = 0; i < SEGLEN; i++) {
        const int t = t0 + i;
        float dtv = dt[(size_t)t * INNER + d];
        float xav = xa[(size_t)t * INNER + d];
        float zv  = xz[(size_t)t * (2 * INNER) + INNER + d];
        float dm  = dtmean[t];
        float bx  = dm * xav;
        float p[NST];
        pow_ladder(__expf(-dtv), p);
        const float4* bp = (const float4*)(bcdtr + (size_t)t * 96);
        float4 b0 = bp[0], b1 = bp[1], b2 = bp[2], b3 = bp[3];
        float4 c0 = bp[4], c1 = bp[5], c2 = bp[6], c3 = bp[7];
        float Bm[NST] = {b0.x, b0.y, b0.z, b0.w, b1.x, b1.y, b1.z, b1.w,
                         b2.x, b2.y, b2.z, b2.w, b3.x, b3.y, b3.z, b3.w};
        float Cm[NST] = {c0.x, c0.y, c0.z, c0.w, c1.x, c1.y, c1.z, c1.w,
                         c2.x, c2.y, c2.z, c2.w, c3.x, c3.y, c3.z, c3.w};
        float y0 = 0.f, y1 = 0.f, y2 = 0.f, y3 = 0.f;
        #pragma unroll
        for (int n = 0; n < NST; n += 4) {
            h[n + 0] = fmaf(p[n + 0], h[n + 0], bx * Bm[n + 0]);
            h[n + 1] = fmaf(p[n + 1], h[n + 1], bx * Bm[n + 1]);
            h[n + 2] = fmaf(p[n + 2], h[n + 2], bx * Bm[n + 2]);
            h[n + 3] = fmaf(p[n + 3], h[n + 3], bx * Bm[n + 3]);
            y0 = fmaf(h[n + 0], Cm[n + 0], y0);
            y1 = fmaf(h[n + 1], Cm[n + 1], y1);
            y2 = fmaf(h[n + 2], Cm[n + 2], y2);
            y3 = fmaf(h[n + 3], Cm[n + 3], y3);
        }
        float y = (y0 + y1) + (y2 + y3);
        float sz = zv / (1.f + __expf(-zv));
        Ao[(size_t)t * INNER + d] = __float2half(y * sz);
    }
}

// ======================= launch =============================================
extern "C" void kernel_launch(void* const* d_in, const int* in_sizes, int n_in,
                              void* d_out, int out_size) {
    const float* x      = (const float*)d_in[0];
    const float* norm_w = (const float*)d_in[1];
    const float* norm_b = (const float*)d_in[2];
    const float* in_w   = (const float*)d_in[3];
    const float* in_b   = (const float*)d_in[4];
    const float* conv_w = (const float*)d_in[5];
    const float* conv_b = (const float*)d_in[6];
    const float* bc_w   = (const float*)d_in[7];
    const float* bc_b   = (const float*)d_in[8];
    const float* dtr_w  = (const float*)d_in[9];
    const float* dtr_b  = (const float*)d_in[10];
    const float* dt_w   = (const float*)d_in[11];
    const float* dt_b   = (const float*)d_in[12];
    const float* out_w  = (const float*)d_in[13];
    const float* out_b  = (const float*)d_in[14];
    float* out = (float*)d_out;

    __half *pA_in, *pB_in, *pA_dtr, *pB_dt, *pA_out, *pB_out;
    float *pxz, *pxa, *pbcdtr, *pdt, *pdtm;
    cudaGetSymbolAddress((void**)&pA_in,  gA_in);
    cudaGetSymbolAddress((void**)&pB_in,  gB_in);
    cudaGetSymbolAddress((void**)&pxz,    g_xz);
    cudaGetSymbolAddress((void**)&pxa,    g_xa);
    cudaGetSymbolAddress((void**)&pbcdtr, g_bcdtr);
    cudaGetSymbolAddress((void**)&pA_dtr, gA_dtr);
    cudaGetSymbolAddress((void**)&pB_dt,  gB_dt);
    cudaGetSymbolAddress((void**)&pdt,    g_dt);
    cudaGetSymbolAddress((void**)&pdtm,   g_dtmean);
    cudaGetSymbolAddress((void**)&pA_out, gA_out);
    cudaGetSymbolAddress((void**)&pB_out, gB_out);

    const int DSMEM = 2 * BUFE * 2;  // 73728 bytes
    cudaFuncSetAttribute(gemm_h<0>, cudaFuncAttributeMaxDynamicSharedMemorySize, DSMEM);
    cudaFuncSetAttribute(gemm_h<1>, cudaFuncAttributeMaxDynamicSharedMemorySize, DSMEM);

    // weight conversions
    wconv_k<<<(2 * INNER) * (H / 8) / 256, 256>>>(in_w, pB_in, 2 * INNER, H);
    wconv_k<<<INNER * (DTR / 8) / 256, 256>>>(dt_w, pB_dt, INNER, DTR);
    wconv_k<<<H * (INNER / 8) / 256, 256>>>(out_w, pB_out, H, INNER);

    // 1. LayerNorm -> fp16 A
    layernorm_h_k<<<TOK, 256>>>(x, norm_w, norm_b, pA_in);
    // 2. in-proj GEMM (M=2048, N=4096, K=1024)
    gemm_h<0><<<dim3(4096 / 128, TOK / 128), 256, DSMEM>>>(
        pA_in, pB_in, in_b, pxz, H, 2 * INNER, 2 * INNER);
    // 3. conv + SiLU -> xa fp32
    conv_silu_k<<<(TOK * INNER) / 256, 256>>>(pxz, conv_w, conv_b, pxa);
    // 4. fp32 bc + dtr projection (M=2048, N=96, K=2048)
    bcproj_k<<<TOK / 16, 256>>>(pxa, bc_w, dtr_w, bc_b, dtr_b, pbcdtr);
    // 5. dtr -> fp16 A
    dtr_h_k<<<TOK * DTR / 256, 256>>>(pbcdtr, pA_dtr);
    // 6. dt GEMM (M=2048, N=2048, K=64) with fused softplus+clip
    gemm_h<1><<<dim3(INNER / 128, TOK / 128), 256, DSMEM>>>(
        pA_dtr, pB_dt, dt_b, pdt, DTR, INNER, INNER);
    // 7. per-token mean of dt
    mean_k<<<TOK, 256>>>(pdt, pdtm);
    // 8. segmented parallel scan + gating -> fp16 A
    scan_k<<<dim3(INNER / 32, BATCH), 256>>>(pdt, pxa, pdtm, pbcdtr, pxz, pA_out);
    // 9. out-proj GEMM (M=2048, N=1024, K=2048)
    gemm_h<0><<<dim3(H / 128, TOK / 128), 256, DSMEM>>>(
        pA_out, pB_out, out_b, out, INNER, H, H);
}

// round 6
// speedup vs baseline: 3.5368x; 1.1688x over previous
#include <cuda_runtime.h>
#include <cuda_fp16.h>
#include <cstdint>
#include <math.h>

#define H      1024
#define INNER  2048
#define NST    16
#define DTR    64
#define BATCH  2
#define SEQ    1024
#define TOK    (BATCH*SEQ)   // 2048

// ======================= PTX helpers (plain sm_103 legal) ====================
__device__ __forceinline__ uint32_t smem_u32(const void* p) {
    uint32_t a;
    asm("{ .reg .u64 t; cvta.to.shared.u64 t, %1; cvt.u32.u64 %0, t; }"
        : "=r"(a) : "l"(p));
    return a;
}
__device__ __forceinline__ void cp16(uint32_t saddr, const void* g) {
    asm volatile("cp.async.cg.shared.global [%0], [%1], 16;"
                 :: "r"(saddr), "l"(g) : "memory");
}
#define CP_COMMIT() asm volatile("cp.async.commit_group;" ::: "memory")
#define CP_WAIT1()  asm volatile("cp.async.wait_group 1;" ::: "memory")

__device__ __forceinline__ void ldsm_x4(uint32_t* r, uint32_t addr) {
    asm volatile("ldmatrix.sync.aligned.m8n8.x4.shared.b16 {%0,%1,%2,%3}, [%4];"
                 : "=r"(r[0]), "=r"(r[1]), "=r"(r[2]), "=r"(r[3]) : "r"(addr));
}
__device__ __forceinline__ void mma_f16(float* c, const uint32_t* a, const uint32_t* b) {
    asm volatile("mma.sync.aligned.m16n8k16.row.col.f32.f16.f16.f32 "
                 "{%0,%1,%2,%3}, {%4,%5,%6,%7}, {%8,%9}, {%0,%1,%2,%3};"
                 : "+f"(c[0]), "+f"(c[1]), "+f"(c[2]), "+f"(c[3])
                 : "r"(a[0]), "r"(a[1]), "r"(a[2]), "r"(a[3]),
                   "r"(b[0]), "r"(b[1]));
}

// ======================= scratch buffers ====================================
__device__ __align__(16) __half gA_in [TOK * H];
__device__ __align__(16) __half gB_in [2 * INNER * H];
__device__ __align__(16) float  g_xz  [TOK * 2 * INNER];
__device__ __align__(16) float  g_xa  [TOK * INNER];
__device__ __align__(16) float  g_bcdtr[TOK * 96];
__device__ __align__(16) __half gA_dtr[TOK * DTR];
__device__ __align__(16) __half gB_dt [INNER * DTR];
__device__ __align__(16) float  g_dt  [TOK * INNER];
__device__                float g_dtmean[TOK];
__device__ __align__(16) __half gA_out[TOK * INNER];
__device__ __align__(16) __half gB_out[H * INNER];

// ======================= warp-MMA fp16 GEMM (3-stage pipeline) ==============
// C[M,N] = A[M,K]*B[N,K]^T + bias.  BM=BN=128, BK=64, 256 threads.
// EPI = 0: plain; EPI = 1: softplus+clip (dt path).
#define BM    128
#define BN    128
#define BKE   64
#define LDSTR 72
#define BUFE  ((BM + BN) * LDSTR)    // halfs per stage
#define STGB  (BUFE * 2)             // bytes per stage (36864)
#define NSTG  3

template <int EPI>
__global__ void __launch_bounds__(256, 2)
gemm_h(const __half* __restrict__ A, const __half* __restrict__ B,
       const float* __restrict__ bias, float* __restrict__ C,
       int K, int ldc, int nvalid) {
    extern __shared__ __align__(16) __half sm[];
    const uint32_t smb = smem_u32(sm);

    const int tid = threadIdx.x;
    const int lane = tid & 31, wid = tid >> 5;
    const int m0 = blockIdx.y * BM, n0 = blockIdx.x * BN;
    const int wm = (wid & 3) * 32;
    const int wn = (wid >> 2) * 64;

    float acc[2][8][4];
    #pragma unroll
    for (int i = 0; i < 2; i++)
        #pragma unroll
        for (int j = 0; j < 8; j++)
            #pragma unroll
            for (int k = 0; k < 4; k++) acc[i][j][k] = 0.f;

    const int nc = K >> 6;

    auto load_tile = [&](int stg, int kc) {
        const __half* Ag = A + (size_t)m0 * K + kc * BKE;
        const __half* Bg = B + (size_t)n0 * K + kc * BKE;
        uint32_t sa = smb + stg * STGB;
        uint32_t sbb = sa + BM * LDSTR * 2;
        #pragma unroll
        for (int i = 0; i < 4; i++) {
            int ci = tid + i * 256;
            int row = ci >> 3, c8 = ci & 7;
            uint32_t so = (uint32_t)(row * LDSTR + c8 * 8) * 2;
            cp16(sa + so,  Ag + (size_t)row * K + c8 * 8);
            cp16(sbb + so, Bg + (size_t)row * K + c8 * 8);
        }
    };

    // prologue: keep 2 stages in flight (empty group if nc == 1)
    load_tile(0, 0);
    CP_COMMIT();
    if (nc > 1) load_tile(1, 1);
    CP_COMMIT();

    int cs = 0, ls = 2;
    for (int c = 0; c < nc; c++) {
        CP_WAIT1();                       // oldest group (stage cs) complete
        __syncthreads();
        if (c + 2 < nc) {
            load_tile(ls, c + 2);
            ls = (ls + 1 == NSTG) ? 0 : ls + 1;
        }
        CP_COMMIT();                      // commit (possibly empty) each iter

        const uint32_t a_base = smb + cs * STGB;
        const uint32_t b_base = a_base + BM * LDSTR * 2;

        #pragma unroll
        for (int kk = 0; kk < 4; kk++) {
            uint32_t afr[2][4];
            #pragma unroll
            for (int mt = 0; mt < 2; mt++) {
                int row = wm + mt * 16 + (lane & 15);
                int col = kk * 16 + (lane >> 4) * 8;
                ldsm_x4(afr[mt], a_base + (uint32_t)(row * LDSTR + col) * 2);
            }
            uint32_t bfr[8][2];
            #pragma unroll
            for (int p = 0; p < 4; p++) {
                int g = lane >> 3, idx = lane & 7;
                int row = wn + p * 16 + idx + (g >> 1) * 8;
                int col = kk * 16 + (g & 1) * 8;
                uint32_t r[4];
                ldsm_x4(r, b_base + (uint32_t)(row * LDSTR + col) * 2);
                bfr[2 * p][0] = r[0];     bfr[2 * p][1] = r[1];
                bfr[2 * p + 1][0] = r[2]; bfr[2 * p + 1][1] = r[3];
            }
            #pragma unroll
            for (int mt = 0; mt < 2; mt++)
                #pragma unroll
                for (int nt = 0; nt < 8; nt++)
                    mma_f16(acc[mt][nt], afr[mt], bfr[nt]);
        }
        cs = (cs + 1 == NSTG) ? 0 : cs + 1;
    }

    #pragma unroll
    for (int mt = 0; mt < 2; mt++) {
        #pragma unroll
        for (int nt = 0; nt < 8; nt++) {
            int row = m0 + wm + mt * 16 + (lane >> 2);
            int col = n0 + wn + nt * 8 + (lane & 3) * 2;
            if (col < nvalid) {
                float b0 = bias[col], b1 = bias[col + 1];
                float v00 = acc[mt][nt][0] + b0, v01 = acc[mt][nt][1] + b1;
                float v10 = acc[mt][nt][2] + b0, v11 = acc[mt][nt][3] + b1;
                if (EPI == 1) {
                    v00 = (v00 > 20.f) ? v00 : log1pf(__expf(v00));
                    v01 = (v01 > 20.f) ? v01 : log1pf(__expf(v01));
                    v10 = (v10 > 20.f) ? v10 : log1pf(__expf(v10));
                    v11 = (v11 > 20.f) ? v11 : log1pf(__expf(v11));
                    v00 = fminf(fmaxf(v00, 0.001f), 0.1f);
                    v01 = fminf(fmaxf(v01, 0.001f), 0.1f);
                    v10 = fminf(fmaxf(v10, 0.001f), 0.1f);
                    v11 = fminf(fmaxf(v11, 0.001f), 0.1f);
                }
                *(float2*)(C + (size_t)row * ldc + col) = make_float2(v00, v01);
                *(float2*)(C + (size_t)(row + 8) * ldc + col) = make_float2(v10, v11);
            }
        }
    }
}

// ======================= weight conversion (fp32 -> fp16, transposed) =======
__global__ void wconv_k(const float* __restrict__ W, __half* __restrict__ Bo,
                        int N, int K) {
    int gi = blockIdx.x * 256 + threadIdx.x;
    if (gi >= N * (K >> 3)) return;
    int n = gi % N;
    int k0 = (gi / N) * 8;
    __align__(16) __half hv[8];
    #pragma unroll
    for (int i = 0; i < 8; i++)
        hv[i] = __float2half(W[(size_t)(k0 + i) * N + n]);
    *(uint4*)(Bo + (size_t)n * K + k0) = *(uint4*)hv;
}

// ======================= fp32 bc+dtr projection (+ fp16 dtr emit) ===========
__global__ void __launch_bounds__(256)
bcproj_k(const float* __restrict__ xa,
         const float* __restrict__ bcw, const float* __restrict__ dtw,
         const float* __restrict__ bcb, const float* __restrict__ dtrb,
         float* __restrict__ outp, __half* __restrict__ dtr16) {
    __shared__ float sW[64][100];
    __shared__ float sA[16][65];
    const int tid = threadIdx.x;
    const int r = tid >> 4, jg = tid & 15;
    const int m0 = blockIdx.x * 16;

    float acc[6];
    #pragma unroll
    for (int c = 0; c < 6; c++) acc[c] = 0.f;

    for (int k0 = 0; k0 < INNER; k0 += 64) {
        __syncthreads();
        for (int idx = tid; idx < 64 * 96; idx += 256) {
            int kl = idx / 96, j = idx % 96;
            float v = (j < 32) ? bcw[(size_t)(k0 + kl) * 32 + j]
                               : dtw[(size_t)(k0 + kl) * 64 + (j - 32)];
            sW[kl][j] = v;
        }
        for (int idx = tid; idx < 16 * 64; idx += 256) {
            int rr = idx >> 6, kl = idx & 63;
            sA[rr][kl] = xa[(size_t)(m0 + rr) * INNER + k0 + kl];
        }
        __syncthreads();
        #pragma unroll 8
        for (int kl = 0; kl < 64; kl++) {
            float a = sA[r][kl];
            const float* wrow = &sW[kl][jg * 6];
            float2 w01 = *(const float2*)(wrow);
            float2 w23 = *(const float2*)(wrow + 2);
            float2 w45 = *(const float2*)(wrow + 4);
            acc[0] = fmaf(a, w01.x, acc[0]);
            acc[1] = fmaf(a, w01.y, acc[1]);
            acc[2] = fmaf(a, w23.x, acc[2]);
            acc[3] = fmaf(a, w23.y, acc[3]);
            acc[4] = fmaf(a, w45.x, acc[4]);
            acc[5] = fmaf(a, w45.y, acc[5]);
        }
    }
    #pragma unroll
    for (int c = 0; c < 6; c++) {
        int j = jg * 6 + c;
        float bv = (j < 32) ? bcb[j] : dtrb[j - 32];
        float v = acc[c] + bv;
        outp[(size_t)(m0 + r) * 96 + j] = v;
        if (j >= 32)
            dtr16[(size_t)(m0 + r) * 64 + (j - 32)] = __float2half(v);
    }
}

// ======================= LayerNorm -> fp16 A ================================
__global__ void layernorm_h_k(const float* __restrict__ x,
                              const float* __restrict__ w,
                              const float* __restrict__ b,
                              __half* __restrict__ Ao) {
    int row = blockIdx.x;
    const float* xr = x + (size_t)row * H;
    float s = 0.f, s2 = 0.f;
    for (int i = threadIdx.x; i < H; i += 256) {
        float v = xr[i];
        s += v; s2 += v * v;
    }
    #pragma unroll
    for (int o = 16; o > 0; o >>= 1) {
        s  += __shfl_down_sync(0xffffffffu, s,  o);
        s2 += __shfl_down_sync(0xffffffffu, s2, o);
    }
    __shared__ float rs[8], rs2[8], stat[2];
    int wid = threadIdx.x >> 5, lid = threadIdx.x & 31;
    if (lid == 0) { rs[wid] = s; rs2[wid] = s2; }
    __syncthreads();
    if (threadIdx.x == 0) {
        float a = 0.f, c = 0.f;
        #pragma unroll
        for (int i = 0; i < 8; i++) { a += rs[i]; c += rs2[i]; }
        float mu = a / (float)H;
        stat[0] = mu;
        stat[1] = rsqrtf(c / (float)H - mu * mu + 1e-5f);
    }
    __syncthreads();
    float mu = stat[0], rstd = stat[1];
    for (int i = threadIdx.x; i < H; i += 256)
        Ao[(size_t)row * H + i] = __float2half((xr[i] - mu) * rstd * w[i] + b[i]);
}

// ======================= conv(4-tap)+SiLU -> xa fp32 ========================
__global__ void conv_silu_k(const float* __restrict__ xz,
                            const float* __restrict__ cw,
                            const float* __restrict__ cb,
                            float* __restrict__ xa) {
    int idx = blockIdx.x * 256 + threadIdx.x;
    int d = idx & (INNER - 1);
    int tg = idx >> 11;
    int b = tg >> 10;
    int t = tg & (SEQ - 1);
    float4 w4 = *(const float4*)(cw + d * 4);
    float wv[4] = {w4.x, w4.y, w4.z, w4.w};
    float acc = cb[d];
    #pragma unroll
    for (int k = 0; k < 4; k++) {
        int tt = t - 3 + k;
        if (tt >= 0)
            acc = fmaf(xz[((size_t)(b * SEQ + tt)) * (2 * INNER) + d], wv[k], acc);
    }
    xa[idx] = acc / (1.f + __expf(-acc));
}

// ======================= per-token mean of clipped dt ========================
__global__ void mean_k(const float* __restrict__ dt, float* __restrict__ m) {
    int t = blockIdx.x;
    float s = 0.f;
    for (int i = threadIdx.x; i < INNER; i += 256)
        s += dt[(size_t)t * INNER + i];
    #pragma unroll
    for (int o = 16; o > 0; o >>= 1)
        s += __shfl_down_sync(0xffffffffu, s, o);
    __shared__ float rs[8];
    int wid = threadIdx.x >> 5, lid = threadIdx.x & 31;
    if (lid == 0) rs[wid] = s;
    __syncthreads();
    if (threadIdx.x == 0) {
        float a = 0.f;
        #pragma unroll
        for (int i = 0; i < 8; i++) a += rs[i];
        m[t] = a / (float)INNER;
    }
}

// ======================= segmented parallel scan + gating ====================
#define SEGS   8
#define SEGLEN 128

__device__ __forceinline__ void pow_ladder(float e1, float* p) {
    float e2 = e1 * e1, e4 = e2 * e2, e8 = e4 * e4;
    p[0] = e1;       p[1] = e2;       p[2] = e2 * e1;  p[3] = e4;
    p[4] = e4 * e1;  p[5] = e4 * e2;  p[6] = e4 * p[2]; p[7] = e8;
    p[8] = e8 * e1;  p[9] = e8 * e2;  p[10] = e8 * p[2]; p[11] = e8 * e4;
    p[12] = e8 * p[4]; p[13] = e8 * p[5]; p[14] = e8 * p[6]; p[15] = e8 * e8;
}

__global__ void __launch_bounds__(256)
scan_k(const float* __restrict__ dt,
       const float* __restrict__ xa,
       const float* __restrict__ dtmean,
       const float* __restrict__ bcdtr,
       const float* __restrict__ xz,
       __half* __restrict__ Ao) {
    __shared__ float shH[SEGS][32][NST];
    __shared__ float shS[SEGS][32];

    const int tid = threadIdx.x;
    const int dlane = tid & 31, s = tid >> 5;
    const int b = blockIdx.y;
    const int d = blockIdx.x * 32 + dlane;
    const int t0 = b * SEQ + s * SEGLEN;

    float h[NST];
    #pragma unroll
    for (int n = 0; n < NST; n++) h[n] = 0.f;
    float sdt = 0.f;

    for (int i = 0; i < SEGLEN; i++) {
        const int t = t0 + i;
        float dtv = dt[(size_t)t * INNER + d];
        float xav = xa[(size_t)t * INNER + d];
        float dm  = dtmean[t];
        float bx  = dm * xav;
        sdt += dtv;
        float p[NST];
        pow_ladder(__expf(-dtv), p);
        const float4* bp = (const float4*)(bcdtr + (size_t)t * 96);
        float4 b0 = bp[0], b1 = bp[1], b2 = bp[2], b3 = bp[3];
        float Bm[NST] = {b0.x, b0.y, b0.z, b0.w, b1.x, b1.y, b1.z, b1.w,
                         b2.x, b2.y, b2.z, b2.w, b3.x, b3.y, b3.z, b3.w};
        #pragma unroll
        for (int n = 0; n < NST; n++)
            h[n] = fmaf(p[n], h[n], bx * Bm[n]);
    }
    shS[s][dlane] = sdt;
    #pragma unroll
    for (int n = 0; n < NST; n++) shH[s][dlane][n] = h[n];
    __syncthreads();

    float hin[NST];
    #pragma unroll
    for (int n = 0; n < NST; n++) hin[n] = 0.f;
    for (int j = 0; j < s; j++) {
        float p[NST];
        pow_ladder(__expf(-shS[j][dlane]), p);
        #pragma unroll
        for (int n = 0; n < NST; n++)
            hin[n] = fmaf(p[n], hin[n], shH[j][dlane][n]);
    }

    #pragma unroll
    for (int n = 0; n < NST; n++) h[n] = hin[n];

    for (int i = 0; i < SEGLEN; i++) {
        const int t = t0 + i;
        float dtv = dt[(size_t)t * INNER + d];
        float xav = xa[(size_t)t * INNER + d];
        float zv  = xz[(size_t)t * (2 * INNER) + INNER + d];
        float dm  = dtmean[t];
        float bx  = dm * xav;
        float p[NST];
        pow_ladder(__expf(-dtv), p);
        const float4* bp = (const float4*)(bcdtr + (size_t)t * 96);
        float4 b0 = bp[0], b1 = bp[1], b2 = bp[2], b3 = bp[3];
        float4 c0 = bp[4], c1 = bp[5], c2 = bp[6], c3 = bp[7];
        float Bm[NST] = {b0.x, b0.y, b0.z, b0.w, b1.x, b1.y, b1.z, b1.w,
                         b2.x, b2.y, b2.z, b2.w, b3.x, b3.y, b3.z, b3.w};
        float Cm[NST] = {c0.x, c0.y, c0.z, c0.w, c1.x, c1.y, c1.z, c1.w,
                         c2.x, c2.y, c2.z, c2.w, c3.x, c3.y, c3.z, c3.w};
        float y0 = 0.f, y1 = 0.f, y2 = 0.f, y3 = 0.f;
        #pragma unroll
        for (int n = 0; n < NST; n += 4) {
            h[n + 0] = fmaf(p[n + 0], h[n + 0], bx * Bm[n + 0]);
            h[n + 1] = fmaf(p[n + 1], h[n + 1], bx * Bm[n + 1]);
            h[n + 2] = fmaf(p[n + 2], h[n + 2], bx * Bm[n + 2]);
            h[n + 3] = fmaf(p[n + 3], h[n + 3], bx * Bm[n + 3]);
            y0 = fmaf(h[n + 0], Cm[n + 0], y0);
            y1 = fmaf(h[n + 1], Cm[n + 1], y1);
            y2 = fmaf(h[n + 2], Cm[n + 2], y2);
            y3 = fmaf(h[n + 3], Cm[n + 3], y3);
        }
        float y = (y0 + y1) + (y2 + y3);
        float sz = zv / (1.f + __expf(-zv));
        Ao[(size_t)t * INNER + d] = __float2half(y * sz);
    }
}

// ======================= launch =============================================
extern "C" void kernel_launch(void* const* d_in, const int* in_sizes, int n_in,
                              void* d_out, int out_size) {
    const float* x      = (const float*)d_in[0];
    const float* norm_w = (const float*)d_in[1];
    const float* norm_b = (const float*)d_in[2];
    const float* in_w   = (const float*)d_in[3];
    const float* in_b   = (const float*)d_in[4];
    const float* conv_w = (const float*)d_in[5];
    const float* conv_b = (const float*)d_in[6];
    const float* bc_w   = (const float*)d_in[7];
    const float* bc_b   = (const float*)d_in[8];
    const float* dtr_w  = (const float*)d_in[9];
    const float* dtr_b  = (const float*)d_in[10];
    const float* dt_w   = (const float*)d_in[11];
    const float* dt_b   = (const float*)d_in[12];
    const float* out_w  = (const float*)d_in[13];
    const float* out_b  = (const float*)d_in[14];
    float* out = (float*)d_out;

    __half *pA_in, *pB_in, *pA_dtr, *pB_dt, *pA_out, *pB_out;
    float *pxz, *pxa, *pbcdtr, *pdt, *pdtm;
    cudaGetSymbolAddress((void**)&pA_in,  gA_in);
    cudaGetSymbolAddress((void**)&pB_in,  gB_in);
    cudaGetSymbolAddress((void**)&pxz,    g_xz);
    cudaGetSymbolAddress((void**)&pxa,    g_xa);
    cudaGetSymbolAddress((void**)&pbcdtr, g_bcdtr);
    cudaGetSymbolAddress((void**)&pA_dtr, gA_dtr);
    cudaGetSymbolAddress((void**)&pB_dt,  gB_dt);
    cudaGetSymbolAddress((void**)&pdt,    g_dt);
    cudaGetSymbolAddress((void**)&pdtm,   g_dtmean);
    cudaGetSymbolAddress((void**)&pA_out, gA_out);
    cudaGetSymbolAddress((void**)&pB_out, gB_out);

    const int DSMEM = NSTG * STGB;  // 110592 bytes
    cudaFuncSetAttribute(gemm_h<0>, cudaFuncAttributeMaxDynamicSharedMemorySize, DSMEM);
    cudaFuncSetAttribute(gemm_h<1>, cudaFuncAttributeMaxDynamicSharedMemorySize, DSMEM);

    // weight conversions
    wconv_k<<<(2 * INNER) * (H / 8) / 256, 256>>>(in_w, pB_in, 2 * INNER, H);
    wconv_k<<<INNER * (DTR / 8) / 256, 256>>>(dt_w, pB_dt, INNER, DTR);
    wconv_k<<<H * (INNER / 8) / 256, 256>>>(out_w, pB_out, H, INNER);

    // 1. LayerNorm -> fp16 A
    layernorm_h_k<<<TOK, 256>>>(x, norm_w, norm_b, pA_in);
    // 2. in-proj GEMM (M=2048, N=4096, K=1024)
    gemm_h<0><<<dim3(4096 / 128, TOK / 128), 256, DSMEM>>>(
        pA_in, pB_in, in_b, pxz, H, 2 * INNER, 2 * INNER);
    // 3. conv + SiLU -> xa fp32
    conv_silu_k<<<(TOK * INNER) / 256, 256>>>(pxz, conv_w, conv_b, pxa);
    // 4. fp32 bc + dtr projection, fused fp16 dtr emit
    bcproj_k<<<TOK / 16, 256>>>(pxa, bc_w, dtr_w, bc_b, dtr_b, pbcdtr, pA_dtr);
    // 5. dt GEMM (M=2048, N=2048, K=64) with fused softplus+clip
    gemm_h<1><<<dim3(INNER / 128, TOK / 128), 256, DSMEM>>>(
        pA_dtr, pB_dt, dt_b, pdt, DTR, INNER, INNER);
    // 6. per-token mean of dt
    mean_k<<<TOK, 256>>>(pdt, pdtm);
    // 7. segmented parallel scan + gating -> fp16 A
    scan_k<<<dim3(INNER / 32, BATCH), 256>>>(pdt, pxa, pdtm, pbcdtr, pxz, pA_out);
    // 8. out-proj GEMM (M=2048, N=1024, K=2048)
    gemm_h<0><<<dim3(H / 128, TOK / 128), 256, DSMEM>>>(
        pA_out, pB_out, out_b, out, INNER, H, H);
}